// round 1
// baseline (speedup 1.0000x reference)
#include <cuda_runtime.h>
#include <math.h>
#include <stdint.h>

#define BB 2
#define TT 2048
#define CC 1024
#define HH 16
#define DH 64
#define SCALE 0.125f   // DH^-0.5

// Scratch (device globals: allocation-free rule)
__device__ float g_qkv[3u * BB * HH * TT * DH];   // [s][b][h][t][d]
__device__ float g_attn_out[(size_t)BB * TT * CC]; // [b*t][c] with c = h*DH+d
__device__ float g_decay[HH * TT];                 // [h][dist]

// ---------------------------------------------------------------------------
// Decay table: decay[h][dist] = exp(-softplus(lambda_raw[h]) * dist)
// ---------------------------------------------------------------------------
__global__ void decay_kernel(const float* __restrict__ lambda_raw) {
    int idx = blockIdx.x * blockDim.x + threadIdx.x;
    if (idx < HH * TT) {
        int h = idx / TT;
        int d = idx % TT;
        float lam = log1pf(expf(lambda_raw[h]));
        g_decay[idx] = expf(-lam * (float)d);
    }
}

// ---------------------------------------------------------------------------
// Generic NT GEMM: C[m][n] = sum_k A[m][k]*Bw[n][k] + bias[n]
// 128x128 tile, BK=16, 256 threads, 8x8 micro-tile.
// EPI 0: scatter into g_qkv layout. EPI 1: plain row-major store.
// ---------------------------------------------------------------------------
template <int EPI>
__launch_bounds__(256)
__global__ void gemm_nt(const float* __restrict__ A, const float* __restrict__ Bw,
                        const float* __restrict__ bias, float* __restrict__ Cout,
                        int M, int N, int K) {
    __shared__ float sA[16 * 128];
    __shared__ float sB[16 * 128];

    const int tid = threadIdx.x;
    const int n0 = blockIdx.x * 128;
    const int m0 = blockIdx.y * 128;
    const int r0 = (tid >> 4) * 8;
    const int c0 = (tid & 15) * 8;

    float acc[8][8];
#pragma unroll
    for (int i = 0; i < 8; i++)
#pragma unroll
        for (int j = 0; j < 8; j++) acc[i][j] = 0.f;

    for (int k0 = 0; k0 < K; k0 += 16) {
        __syncthreads();
#pragma unroll
        for (int i = 0; i < 2; i++) {
            int f = tid + i * 256;       // 0..511 float4 slots
            int row = f >> 2;            // 4 float4 per row (16 floats)
            int k4 = f & 3;
            float4 va = *(const float4*)&A[(size_t)(m0 + row) * K + k0 + k4 * 4];
            sA[(k4 * 4 + 0) * 128 + row] = va.x;
            sA[(k4 * 4 + 1) * 128 + row] = va.y;
            sA[(k4 * 4 + 2) * 128 + row] = va.z;
            sA[(k4 * 4 + 3) * 128 + row] = va.w;
            float4 vb = *(const float4*)&Bw[(size_t)(n0 + row) * K + k0 + k4 * 4];
            sB[(k4 * 4 + 0) * 128 + row] = vb.x;
            sB[(k4 * 4 + 1) * 128 + row] = vb.y;
            sB[(k4 * 4 + 2) * 128 + row] = vb.z;
            sB[(k4 * 4 + 3) * 128 + row] = vb.w;
        }
        __syncthreads();
#pragma unroll
        for (int kk = 0; kk < 16; kk++) {
            float4 a0 = *(const float4*)&sA[kk * 128 + r0];
            float4 a1 = *(const float4*)&sA[kk * 128 + r0 + 4];
            float4 b0 = *(const float4*)&sB[kk * 128 + c0];
            float4 b1 = *(const float4*)&sB[kk * 128 + c0 + 4];
            float av[8] = {a0.x, a0.y, a0.z, a0.w, a1.x, a1.y, a1.z, a1.w};
            float bv[8] = {b0.x, b0.y, b0.z, b0.w, b1.x, b1.y, b1.z, b1.w};
#pragma unroll
            for (int i = 0; i < 8; i++)
#pragma unroll
                for (int j = 0; j < 8; j++) acc[i][j] = fmaf(av[i], bv[j], acc[i][j]);
        }
    }

#pragma unroll
    for (int i = 0; i < 8; i++) {
        int tr = m0 + r0 + i;
#pragma unroll
        for (int j = 0; j < 8; j++) {
            int o = n0 + c0 + j;
            float v = acc[i][j] + bias[o];
            if (EPI == 0) {
                // o = (s*H + h)*DH + d ; tr = b*T + t
                int s = o >> 10;
                int rem = o & 1023;
                int h = rem >> 6;
                int d = rem & 63;
                int b = tr >> 11;
                int t = tr & 2047;
                g_qkv[(size_t)s * (BB * HH * TT * DH) +
                      ((size_t)(b * HH + h) * TT + t) * DH + d] = v;
            } else {
                Cout[(size_t)tr * N + o] = v;
            }
        }
    }
}

// ---------------------------------------------------------------------------
// Flash attention with multiplicative per-head decay on logits.
// Grid: (T/128, B*H). 256 threads. BM=BN=128.
// smem: Qt[64][128] | Kt[64][128] | V[128][64] | P[128][128]  (160 KB)
// ---------------------------------------------------------------------------
__device__ __forceinline__ float rmax16(float v) {
#pragma unroll
    for (int m = 8; m > 0; m >>= 1) v = fmaxf(v, __shfl_xor_sync(0xffffffffu, v, m, 16));
    return v;
}
__device__ __forceinline__ float rsum16(float v) {
#pragma unroll
    for (int m = 8; m > 0; m >>= 1) v += __shfl_xor_sync(0xffffffffu, v, m, 16);
    return v;
}

#define FLASH_SMEM (size_t)((64 * 128 + 64 * 128 + 128 * 64 + 128 * 128) * sizeof(float))

__launch_bounds__(256)
__global__ void flash_kernel() {
    extern __shared__ float smem[];
    float* sQ = smem;                 // [kk][row] 64x128
    float* sK = sQ + 64 * 128;        // [kk][col] 64x128
    float* sV = sK + 64 * 128;        // [col][d]  128x64
    float* sP = sV + 128 * 64;        // [row][col] 128x128

    const int tid = threadIdx.x;
    const int tx = tid & 15;
    const int r0 = (tid >> 4) * 8;
    const int c0 = tx * 8;
    const int d0 = tx * 4;

    const int bh = blockIdx.y;
    const int b = bh / HH;
    const int h = bh % HH;
    const int i0 = blockIdx.x * 128;

    const size_t plane = (size_t)BB * HH * TT * DH;
    const float* Qg = g_qkv + ((size_t)(b * HH + h) * TT) * DH;
    const float* Kg = Qg + plane;
    const float* Vg = Qg + 2 * plane;
    const float* dec = g_decay + h * TT;

    // Load Q tile transposed
#pragma unroll
    for (int i = 0; i < 8; i++) {
        int f = tid + i * 256;  // 2048 float4 slots (128 rows x 16 f4)
        int row = f >> 4;
        int d4 = f & 15;
        float4 v = *(const float4*)&Qg[(size_t)(i0 + row) * DH + d4 * 4];
        sQ[(d4 * 4 + 0) * 128 + row] = v.x;
        sQ[(d4 * 4 + 1) * 128 + row] = v.y;
        sQ[(d4 * 4 + 2) * 128 + row] = v.z;
        sQ[(d4 * 4 + 3) * 128 + row] = v.w;
    }

    float m_run[8], l_run[8], O[8][4];
#pragma unroll
    for (int i = 0; i < 8; i++) {
        m_run[i] = -1e30f;
        l_run[i] = 0.f;
#pragma unroll
        for (int j = 0; j < 4; j++) O[i][j] = 0.f;
    }

    for (int j0 = 0; j0 < TT; j0 += 128) {
        __syncthreads();
        // Load K (transposed) + V (natural)
#pragma unroll
        for (int i = 0; i < 8; i++) {
            int f = tid + i * 256;
            int row = f >> 4;
            int d4 = f & 15;
            float4 kv = *(const float4*)&Kg[(size_t)(j0 + row) * DH + d4 * 4];
            sK[(d4 * 4 + 0) * 128 + row] = kv.x;
            sK[(d4 * 4 + 1) * 128 + row] = kv.y;
            sK[(d4 * 4 + 2) * 128 + row] = kv.z;
            sK[(d4 * 4 + 3) * 128 + row] = kv.w;
            float4 vv = *(const float4*)&Vg[(size_t)(j0 + row) * DH + d4 * 4];
            *(float4*)&sV[row * DH + d4 * 4] = vv;
        }
        __syncthreads();

        // S = Q K^T  (8x8 micro)
        float s[8][8];
#pragma unroll
        for (int i = 0; i < 8; i++)
#pragma unroll
            for (int j = 0; j < 8; j++) s[i][j] = 0.f;
#pragma unroll 8
        for (int kk = 0; kk < DH; kk++) {
            float4 qa = *(const float4*)&sQ[kk * 128 + r0];
            float4 qb = *(const float4*)&sQ[kk * 128 + r0 + 4];
            float4 ka = *(const float4*)&sK[kk * 128 + c0];
            float4 kb = *(const float4*)&sK[kk * 128 + c0 + 4];
            float qv[8] = {qa.x, qa.y, qa.z, qa.w, qb.x, qb.y, qb.z, qb.w};
            float kv[8] = {ka.x, ka.y, ka.z, ka.w, kb.x, kb.y, kb.z, kb.w};
#pragma unroll
            for (int i = 0; i < 8; i++)
#pragma unroll
                for (int j = 0; j < 8; j++) s[i][j] = fmaf(qv[i], kv[j], s[i][j]);
        }

        // logits = s * scale * decay(|i-j|)
#pragma unroll
        for (int i = 0; i < 8; i++) {
            int gi = i0 + r0 + i;
#pragma unroll
            for (int j = 0; j < 8; j++) {
                int gj = j0 + c0 + j;
                int dist = abs(gi - gj);
                s[i][j] = s[i][j] * SCALE * __ldg(&dec[dist]);
            }
        }

        // Online softmax per row (16 threads per row group)
#pragma unroll
        for (int i = 0; i < 8; i++) {
            float mx = s[i][0];
#pragma unroll
            for (int j = 1; j < 8; j++) mx = fmaxf(mx, s[i][j]);
            mx = rmax16(mx);
            float newm = fmaxf(m_run[i], mx);
            float alpha = __expf(m_run[i] - newm);
            float rs = 0.f;
#pragma unroll
            for (int j = 0; j < 8; j++) {
                float p = __expf(s[i][j] - newm);
                s[i][j] = p;
                rs += p;
            }
            rs = rsum16(rs);
            l_run[i] = l_run[i] * alpha + rs;
            m_run[i] = newm;
#pragma unroll
            for (int j = 0; j < 4; j++) O[i][j] *= alpha;
            // store P row chunk
            float4 p0 = {s[i][0], s[i][1], s[i][2], s[i][3]};
            float4 p1 = {s[i][4], s[i][5], s[i][6], s[i][7]};
            *(float4*)&sP[(r0 + i) * 128 + c0] = p0;
            *(float4*)&sP[(r0 + i) * 128 + c0 + 4] = p1;
        }
        __syncthreads();

        // O += P V  (rows r0..r0+7, cols d0..d0+3)
        for (int c4 = 0; c4 < 128; c4 += 4) {
            float4 v0 = *(const float4*)&sV[(c4 + 0) * DH + d0];
            float4 v1 = *(const float4*)&sV[(c4 + 1) * DH + d0];
            float4 v2 = *(const float4*)&sV[(c4 + 2) * DH + d0];
            float4 v3 = *(const float4*)&sV[(c4 + 3) * DH + d0];
#pragma unroll
            for (int i = 0; i < 8; i++) {
                float4 p = *(const float4*)&sP[(r0 + i) * 128 + c4];
                O[i][0] += p.x * v0.x + p.y * v1.x + p.z * v2.x + p.w * v3.x;
                O[i][1] += p.x * v0.y + p.y * v1.y + p.z * v2.y + p.w * v3.y;
                O[i][2] += p.x * v0.z + p.y * v1.z + p.z * v2.z + p.w * v3.z;
                O[i][3] += p.x * v0.w + p.y * v1.w + p.z * v2.w + p.w * v3.w;
            }
        }
    }

    // Normalize + write to g_attn_out[b*T+t][h*DH + d]
#pragma unroll
    for (int i = 0; i < 8; i++) {
        float inv = 1.f / l_run[i];
        float4 o4 = {O[i][0] * inv, O[i][1] * inv, O[i][2] * inv, O[i][3] * inv};
        size_t off = ((size_t)(b * TT + i0 + r0 + i)) * CC + h * DH + d0;
        *(float4*)&g_attn_out[off] = o4;
    }
}

// ---------------------------------------------------------------------------
extern "C" void kernel_launch(void* const* d_in, const int* in_sizes, int n_in,
                              void* d_out, int out_size) {
    const float* x = (const float*)d_in[0];
    const float* qkv_w = (const float*)d_in[1];
    const float* qkv_b = (const float*)d_in[2];
    const float* proj_w = (const float*)d_in[3];
    const float* proj_b = (const float*)d_in[4];
    const float* lambda_raw = (const float*)d_in[5];
    float* out = (float*)d_out;

    void* ao_ptr = nullptr;
    cudaGetSymbolAddress(&ao_ptr, g_attn_out);

    cudaFuncSetAttribute(flash_kernel, cudaFuncAttributeMaxDynamicSharedMemorySize,
                         (int)FLASH_SMEM);

    decay_kernel<<<(HH * TT + 255) / 256, 256>>>(lambda_raw);

    // QKV: M=B*T=4096, N=3C=3072, K=C=1024
    gemm_nt<0><<<dim3(3072 / 128, 4096 / 128), 256>>>(x, qkv_w, qkv_b, nullptr,
                                                      4096, 3072, 1024);

    flash_kernel<<<dim3(TT / 128, BB * HH), 256, FLASH_SMEM>>>();

    // Proj: M=4096, N=C=1024, K=C=1024
    gemm_nt<1><<<dim3(1024 / 128, 4096 / 128), 256>>>((const float*)ao_ptr, proj_w,
                                                      proj_b, out, 4096, 1024, 1024);
}

// round 3
// speedup vs baseline: 1.3377x; 1.3377x over previous
#include <cuda_runtime.h>
#include <cuda_bf16.h>
#include <math.h>
#include <stdint.h>

#define BB 2
#define TT 2048
#define CC 1024
#define HH 16
#define DH 64
#define SCALE 0.125f   // DH^-0.5

// ---------------------------------------------------------------------------
// Scratch (device globals: allocation-free rule)
// ---------------------------------------------------------------------------
__device__ float g_qkv[3u * BB * HH * TT * DH];    // [s][b][h][t][d] fp32
__device__ float g_attn_out[(size_t)BB * TT * CC]; // [b*t][c]
__device__ float g_decay[HH * TT];                 // [h][dist]

// bf16 hi/lo splits
__device__ __nv_bfloat16 g_x_h[4194304],  g_x_l[4194304];   // x   [4096,1024]
__device__ __nv_bfloat16 g_w1_h[3145728], g_w1_l[3145728];  // qkv_w [3072,1024]
__device__ __nv_bfloat16 g_w2_h[1048576], g_w2_l[1048576];  // proj_w [1024,1024]
__device__ __nv_bfloat16 g_ao_h[4194304], g_ao_l[4194304];  // attn_out [4096,1024]

// ---------------------------------------------------------------------------
// mma.sync helpers (baseline PTX — works on plain sm_103 target)
// ---------------------------------------------------------------------------
__device__ __forceinline__ uint32_t smem_u32(const void* p) {
    uint32_t a;
    asm("{ .reg .u64 t; cvta.to.shared.u64 t, %1; cvt.u32.u64 %0, t; }" : "=r"(a) : "l"(p));
    return a;
}
__device__ __forceinline__ uint32_t swz(uint32_t off) {
    return off ^ ((off >> 3) & 0x70);   // SW128: XOR byte bits[6:4] with [9:7]
}
__device__ __forceinline__ void ldmx4(uint32_t* r, uint32_t addr) {
    asm volatile("ldmatrix.sync.aligned.m8n8.x4.shared.b16 {%0,%1,%2,%3}, [%4];"
                 : "=r"(r[0]), "=r"(r[1]), "=r"(r[2]), "=r"(r[3]) : "r"(addr));
}
__device__ __forceinline__ void mma_bf16(float* c, const uint32_t* a, uint32_t b0, uint32_t b1) {
    asm volatile("mma.sync.aligned.m16n8k16.row.col.f32.bf16.bf16.f32 "
                 "{%0,%1,%2,%3}, {%4,%5,%6,%7}, {%8,%9}, {%0,%1,%2,%3};"
                 : "+f"(c[0]), "+f"(c[1]), "+f"(c[2]), "+f"(c[3])
                 : "r"(a[0]), "r"(a[1]), "r"(a[2]), "r"(a[3]), "r"(b0), "r"(b1));
}

// ---------------------------------------------------------------------------
// bf16 hi/lo split:  hi = bf16(v), lo = bf16(v - hi)
// ---------------------------------------------------------------------------
__global__ void split_bf16(const float* __restrict__ src, __nv_bfloat16* __restrict__ hi,
                           __nv_bfloat16* __restrict__ lo, int n4) {
    int i = blockIdx.x * blockDim.x + threadIdx.x;
    if (i < n4) {
        float4 v = ((const float4*)src)[i];
        __nv_bfloat16 h0 = __float2bfloat16(v.x), h1 = __float2bfloat16(v.y);
        __nv_bfloat16 h2 = __float2bfloat16(v.z), h3 = __float2bfloat16(v.w);
        __nv_bfloat162* H = (__nv_bfloat162*)hi;
        __nv_bfloat162* L = (__nv_bfloat162*)lo;
        H[i * 2]     = __nv_bfloat162(h0, h1);
        H[i * 2 + 1] = __nv_bfloat162(h2, h3);
        L[i * 2]     = __nv_bfloat162(__float2bfloat16(v.x - __bfloat162float(h0)),
                                      __float2bfloat16(v.y - __bfloat162float(h1)));
        L[i * 2 + 1] = __nv_bfloat162(__float2bfloat16(v.z - __bfloat162float(h2)),
                                      __float2bfloat16(v.w - __bfloat162float(h3)));
    }
}

// ---------------------------------------------------------------------------
// Decay table
// ---------------------------------------------------------------------------
__global__ void decay_kernel(const float* __restrict__ lambda_raw) {
    int idx = blockIdx.x * blockDim.x + threadIdx.x;
    if (idx < HH * TT) {
        int h = idx / TT;
        int d = idx % TT;
        float lam = log1pf(expf(lambda_raw[h]));
        g_decay[idx] = expf(-lam * (float)d);
    }
}

// ---------------------------------------------------------------------------
// Tile loader: 128 rows x 64 bf16 (128 B/row), SW128-swizzled 16B stores.
// ---------------------------------------------------------------------------
__device__ __forceinline__ void load_tile_bf16(const __nv_bfloat16* __restrict__ g,
                                               char* sm, int tid) {
#pragma unroll
    for (int i = 0; i < 4; i++) {
        int slot = tid + i * 256;       // 0..1023
        int row = slot >> 3;
        int c16 = slot & 7;
        uint4 v = *(const uint4*)(g + (size_t)row * 1024 + c16 * 8);
        *(uint4*)(sm + swz(row * 128 + c16 * 16)) = v;
    }
}

// ---------------------------------------------------------------------------
// bf16x3 mma.sync NT GEMM:  C[m][n] = sum_k A[m][k]*Bw[n][k] + bias[n]
// 128x128 CTA tile, BK=64, 8 warps: warp tile 32(M) x 64(N).
// smem: AH 0 | AL 16K | BH 32K | BL 48K  (64 KB dynamic)
// EPI 0: scatter into g_qkv layout. EPI 1: row-major store.
// ---------------------------------------------------------------------------
#define OFF_AH 0
#define OFF_AL 16384
#define OFF_BH 32768
#define OFF_BL 49152
#define GEMM_SMEM 65536

template <int EPI>
__launch_bounds__(256)
__global__ void gemm_mma(const __nv_bfloat16* __restrict__ Ah, const __nv_bfloat16* __restrict__ Al,
                         const __nv_bfloat16* __restrict__ Bh, const __nv_bfloat16* __restrict__ Bl,
                         const float* __restrict__ bias, float* __restrict__ Cout, int N) {
    extern __shared__ char smem[];
    const int tid = threadIdx.x;
    const int wid = tid >> 5;
    const int lane = tid & 31;
    const int wm = wid & 3;        // M group (32 rows)
    const int wn = wid >> 2;       // N group (64 cols)
    const int n0 = blockIdx.x * 128;
    const int m0 = blockIdx.y * 128;

    const uint32_t sAh = smem_u32(smem + OFF_AH);
    const uint32_t sAl = smem_u32(smem + OFF_AL);
    const uint32_t sBh = smem_u32(smem + OFF_BH);
    const uint32_t sBl = smem_u32(smem + OFF_BL);

    // ldmatrix lane geometry
    // A (m16k16, .x4): matrices [rows0-7,k0-7][rows8-15,k0-7][rows0-7,k8-15][rows8-15,k8-15]
    const int a_row = (lane & 7) + ((lane >> 3) & 1) * 8;   // within 16-row frag
    const int a_kc  = lane >> 4;                            // 16B chunk within k16
    // B (two n8k16 frags, .x4): [n0-7,k0-7][n0-7,k8-15][n8-15,k0-7][n8-15,k8-15]
    const int b_row = ((lane >> 4) * 8) + (lane & 7);       // within 16-n frag
    const int b_kc  = (lane >> 3) & 1;

    float acc[2][8][4];
#pragma unroll
    for (int i = 0; i < 2; i++)
#pragma unroll
        for (int j = 0; j < 8; j++)
#pragma unroll
            for (int q = 0; q < 4; q++) acc[i][j][q] = 0.f;

    for (int c = 0; c < 16; c++) {        // K = 1024, BK = 64
        const size_t ka = (size_t)c * 64;
        __syncthreads();
        load_tile_bf16(Ah + (size_t)m0 * 1024 + ka, smem + OFF_AH, tid);
        load_tile_bf16(Al + (size_t)m0 * 1024 + ka, smem + OFF_AL, tid);
        load_tile_bf16(Bh + (size_t)n0 * 1024 + ka, smem + OFF_BH, tid);
        load_tile_bf16(Bl + (size_t)n0 * 1024 + ka, smem + OFF_BL, tid);
        __syncthreads();

#pragma unroll
        for (int ks = 0; ks < 4; ks++) {
            uint32_t ah[2][4], al[2][4];
#pragma unroll
            for (int mi = 0; mi < 2; mi++) {
                uint32_t off = swz((wm * 32 + mi * 16 + a_row) * 128 + (ks * 2 + a_kc) * 16);
                ldmx4(ah[mi], sAh + off);
                ldmx4(al[mi], sAl + off);
            }
#pragma unroll
            for (int ng = 0; ng < 4; ng++) {
                uint32_t bh[4], bl[4];
                uint32_t off = swz((wn * 64 + ng * 16 + b_row) * 128 + (ks * 2 + b_kc) * 16);
                ldmx4(bh, sBh + off);
                ldmx4(bl, sBl + off);
#pragma unroll
                for (int mi = 0; mi < 2; mi++) {
                    mma_bf16(acc[mi][2 * ng],     ah[mi], bh[0], bh[1]);
                    mma_bf16(acc[mi][2 * ng],     al[mi], bh[0], bh[1]);
                    mma_bf16(acc[mi][2 * ng],     ah[mi], bl[0], bl[1]);
                    mma_bf16(acc[mi][2 * ng + 1], ah[mi], bh[2], bh[3]);
                    mma_bf16(acc[mi][2 * ng + 1], al[mi], bh[2], bh[3]);
                    mma_bf16(acc[mi][2 * ng + 1], ah[mi], bl[2], bl[3]);
                }
            }
        }
    }

    // Epilogue. acc[mi][j]: rows m0 + wm*32 + mi*16 + lane/4 (+8 for c2,c3),
    // cols n0 + wn*64 + j*8 + (lane&3)*2.
#pragma unroll
    for (int mi = 0; mi < 2; mi++) {
#pragma unroll
        for (int j = 0; j < 8; j++) {
            int row = m0 + wm * 32 + mi * 16 + (lane >> 2);
            int o = n0 + wn * 64 + j * 8 + (lane & 3) * 2;
            float b0 = bias[o], b1 = bias[o + 1];
#pragma unroll
            for (int half = 0; half < 2; half++) {
                int m = row + half * 8;
                float2 v = {acc[mi][j][half * 2] + b0, acc[mi][j][half * 2 + 1] + b1};
                if (EPI == 0) {
                    int s = o >> 10;
                    int rem = o & 1023;
                    int h = rem >> 6;
                    int d = rem & 63;
                    int bb = m >> 11;
                    int t = m & 2047;
                    *(float2*)&g_qkv[(size_t)s * (BB * HH * TT * DH) +
                                     ((size_t)(bb * HH + h) * TT + t) * DH + d] = v;
                } else {
                    *(float2*)&Cout[(size_t)m * N + o] = v;
                }
            }
        }
    }
}

// ---------------------------------------------------------------------------
// Flash attention (SIMT fp32, unchanged)
// ---------------------------------------------------------------------------
__device__ __forceinline__ float rmax16(float v) {
#pragma unroll
    for (int m = 8; m > 0; m >>= 1) v = fmaxf(v, __shfl_xor_sync(0xffffffffu, v, m, 16));
    return v;
}
__device__ __forceinline__ float rsum16(float v) {
#pragma unroll
    for (int m = 8; m > 0; m >>= 1) v += __shfl_xor_sync(0xffffffffu, v, m, 16);
    return v;
}

#define FLASH_SMEM (size_t)((64 * 128 + 64 * 128 + 128 * 64 + 128 * 128) * sizeof(float))

__launch_bounds__(256)
__global__ void flash_kernel() {
    extern __shared__ float fsm[];
    float* sQ = fsm;
    float* sK = sQ + 64 * 128;
    float* sV = sK + 64 * 128;
    float* sP = sV + 128 * 64;

    const int tid = threadIdx.x;
    const int tx = tid & 15;
    const int r0 = (tid >> 4) * 8;
    const int c0 = tx * 8;
    const int d0 = tx * 4;

    const int bh = blockIdx.y;
    const int b = bh / HH;
    const int h = bh % HH;
    const int i0 = blockIdx.x * 128;

    const size_t plane = (size_t)BB * HH * TT * DH;
    const float* Qg = g_qkv + ((size_t)(b * HH + h) * TT) * DH;
    const float* Kg = Qg + plane;
    const float* Vg = Qg + 2 * plane;
    const float* dec = g_decay + h * TT;

#pragma unroll
    for (int i = 0; i < 8; i++) {
        int f = tid + i * 256;
        int row = f >> 4;
        int d4 = f & 15;
        float4 v = *(const float4*)&Qg[(size_t)(i0 + row) * DH + d4 * 4];
        sQ[(d4 * 4 + 0) * 128 + row] = v.x;
        sQ[(d4 * 4 + 1) * 128 + row] = v.y;
        sQ[(d4 * 4 + 2) * 128 + row] = v.z;
        sQ[(d4 * 4 + 3) * 128 + row] = v.w;
    }

    float m_run[8], l_run[8], O[8][4];
#pragma unroll
    for (int i = 0; i < 8; i++) {
        m_run[i] = -1e30f;
        l_run[i] = 0.f;
#pragma unroll
        for (int j = 0; j < 4; j++) O[i][j] = 0.f;
    }

    for (int j0 = 0; j0 < TT; j0 += 128) {
        __syncthreads();
#pragma unroll
        for (int i = 0; i < 8; i++) {
            int f = tid + i * 256;
            int row = f >> 4;
            int d4 = f & 15;
            float4 kv = *(const float4*)&Kg[(size_t)(j0 + row) * DH + d4 * 4];
            sK[(d4 * 4 + 0) * 128 + row] = kv.x;
            sK[(d4 * 4 + 1) * 128 + row] = kv.y;
            sK[(d4 * 4 + 2) * 128 + row] = kv.z;
            sK[(d4 * 4 + 3) * 128 + row] = kv.w;
            float4 vv = *(const float4*)&Vg[(size_t)(j0 + row) * DH + d4 * 4];
            *(float4*)&sV[row * DH + d4 * 4] = vv;
        }
        __syncthreads();

        float s[8][8];
#pragma unroll
        for (int i = 0; i < 8; i++)
#pragma unroll
            for (int j = 0; j < 8; j++) s[i][j] = 0.f;
#pragma unroll 8
        for (int kk = 0; kk < DH; kk++) {
            float4 qa = *(const float4*)&sQ[kk * 128 + r0];
            float4 qb = *(const float4*)&sQ[kk * 128 + r0 + 4];
            float4 ka = *(const float4*)&sK[kk * 128 + c0];
            float4 kb = *(const float4*)&sK[kk * 128 + c0 + 4];
            float qv[8] = {qa.x, qa.y, qa.z, qa.w, qb.x, qb.y, qb.z, qb.w};
            float kv[8] = {ka.x, ka.y, ka.z, ka.w, kb.x, kb.y, kb.z, kb.w};
#pragma unroll
            for (int i = 0; i < 8; i++)
#pragma unroll
                for (int j = 0; j < 8; j++) s[i][j] = fmaf(qv[i], kv[j], s[i][j]);
        }

#pragma unroll
        for (int i = 0; i < 8; i++) {
            int gi = i0 + r0 + i;
#pragma unroll
            for (int j = 0; j < 8; j++) {
                int gj = j0 + c0 + j;
                int dist = abs(gi - gj);
                s[i][j] = s[i][j] * SCALE * __ldg(&dec[dist]);
            }
        }

#pragma unroll
        for (int i = 0; i < 8; i++) {
            float mx = s[i][0];
#pragma unroll
            for (int j = 1; j < 8; j++) mx = fmaxf(mx, s[i][j]);
            mx = rmax16(mx);
            float newm = fmaxf(m_run[i], mx);
            float alpha = __expf(m_run[i] - newm);
            float rs = 0.f;
#pragma unroll
            for (int j = 0; j < 8; j++) {
                float p = __expf(s[i][j] - newm);
                s[i][j] = p;
                rs += p;
            }
            rs = rsum16(rs);
            l_run[i] = l_run[i] * alpha + rs;
            m_run[i] = newm;
#pragma unroll
            for (int j = 0; j < 4; j++) O[i][j] *= alpha;
            float4 p0 = {s[i][0], s[i][1], s[i][2], s[i][3]};
            float4 p1 = {s[i][4], s[i][5], s[i][6], s[i][7]};
            *(float4*)&sP[(r0 + i) * 128 + c0] = p0;
            *(float4*)&sP[(r0 + i) * 128 + c0 + 4] = p1;
        }
        __syncthreads();

        for (int c4 = 0; c4 < 128; c4 += 4) {
            float4 v0 = *(const float4*)&sV[(c4 + 0) * DH + d0];
            float4 v1 = *(const float4*)&sV[(c4 + 1) * DH + d0];
            float4 v2 = *(const float4*)&sV[(c4 + 2) * DH + d0];
            float4 v3 = *(const float4*)&sV[(c4 + 3) * DH + d0];
#pragma unroll
            for (int i = 0; i < 8; i++) {
                float4 p = *(const float4*)&sP[(r0 + i) * 128 + c4];
                O[i][0] += p.x * v0.x + p.y * v1.x + p.z * v2.x + p.w * v3.x;
                O[i][1] += p.x * v0.y + p.y * v1.y + p.z * v2.y + p.w * v3.y;
                O[i][2] += p.x * v0.z + p.y * v1.z + p.z * v2.z + p.w * v3.z;
                O[i][3] += p.x * v0.w + p.y * v1.w + p.z * v2.w + p.w * v3.w;
            }
        }
    }

#pragma unroll
    for (int i = 0; i < 8; i++) {
        float inv = 1.f / l_run[i];
        float4 o4 = {O[i][0] * inv, O[i][1] * inv, O[i][2] * inv, O[i][3] * inv};
        size_t off = ((size_t)(b * TT + i0 + r0 + i)) * CC + h * DH + d0;
        *(float4*)&g_attn_out[off] = o4;
    }
}

// ---------------------------------------------------------------------------
extern "C" void kernel_launch(void* const* d_in, const int* in_sizes, int n_in,
                              void* d_out, int out_size) {
    const float* x = (const float*)d_in[0];
    const float* qkv_w = (const float*)d_in[1];
    const float* qkv_b = (const float*)d_in[2];
    const float* proj_w = (const float*)d_in[3];
    const float* proj_b = (const float*)d_in[4];
    const float* lambda_raw = (const float*)d_in[5];
    float* out = (float*)d_out;

    void *p_ao, *p_xh, *p_xl, *p_w1h, *p_w1l, *p_w2h, *p_w2l, *p_aoh, *p_aol;
    cudaGetSymbolAddress(&p_ao, g_attn_out);
    cudaGetSymbolAddress(&p_xh, g_x_h);   cudaGetSymbolAddress(&p_xl, g_x_l);
    cudaGetSymbolAddress(&p_w1h, g_w1_h); cudaGetSymbolAddress(&p_w1l, g_w1_l);
    cudaGetSymbolAddress(&p_w2h, g_w2_h); cudaGetSymbolAddress(&p_w2l, g_w2_l);
    cudaGetSymbolAddress(&p_aoh, g_ao_h); cudaGetSymbolAddress(&p_aol, g_ao_l);

    cudaFuncSetAttribute(flash_kernel, cudaFuncAttributeMaxDynamicSharedMemorySize,
                         (int)FLASH_SMEM);
    cudaFuncSetAttribute(gemm_mma<0>, cudaFuncAttributeMaxDynamicSharedMemorySize, GEMM_SMEM);
    cudaFuncSetAttribute(gemm_mma<1>, cudaFuncAttributeMaxDynamicSharedMemorySize, GEMM_SMEM);

    decay_kernel<<<(HH * TT + 255) / 256, 256>>>(lambda_raw);

    split_bf16<<<4194304 / 4 / 256, 256>>>(x, (__nv_bfloat16*)p_xh, (__nv_bfloat16*)p_xl,
                                           4194304 / 4);
    split_bf16<<<3145728 / 4 / 256, 256>>>(qkv_w, (__nv_bfloat16*)p_w1h, (__nv_bfloat16*)p_w1l,
                                           3145728 / 4);
    split_bf16<<<1048576 / 4 / 256, 256>>>(proj_w, (__nv_bfloat16*)p_w2h, (__nv_bfloat16*)p_w2l,
                                           1048576 / 4);

    // QKV: M=4096, N=3072, K=1024 -> scatter epilogue
    gemm_mma<0><<<dim3(3072 / 128, 4096 / 128), 256, GEMM_SMEM>>>(
        (const __nv_bfloat16*)p_xh, (const __nv_bfloat16*)p_xl,
        (const __nv_bfloat16*)p_w1h, (const __nv_bfloat16*)p_w1l, qkv_b, nullptr, 3072);

    flash_kernel<<<dim3(TT / 128, BB * HH), 256, FLASH_SMEM>>>();

    split_bf16<<<4194304 / 4 / 256, 256>>>((const float*)p_ao, (__nv_bfloat16*)p_aoh,
                                           (__nv_bfloat16*)p_aol, 4194304 / 4);

    // Proj: M=4096, N=1024, K=1024
    gemm_mma<1><<<dim3(1024 / 128, 4096 / 128), 256, GEMM_SMEM>>>(
        (const __nv_bfloat16*)p_aoh, (const __nv_bfloat16*)p_aol,
        (const __nv_bfloat16*)p_w2h, (const __nv_bfloat16*)p_w2l, proj_b, out, 1024);
}

// round 4
// speedup vs baseline: 2.4517x; 1.8328x over previous
#include <cuda_runtime.h>
#include <cuda_bf16.h>
#include <math.h>
#include <stdint.h>

#define BB 2
#define TT 2048
#define CC 1024
#define HH 16
#define DH 64
#define SCALE 0.125f   // DH^-0.5

// ---------------------------------------------------------------------------
// Scratch (device globals: allocation-free rule)
// ---------------------------------------------------------------------------
__device__ float g_decay[HH * TT];                 // [h][dist]

// Q/K: [b][h][t][d] bf16 hi/lo.  V: transposed [b][h][d][t] hi/lo.
__device__ __nv_bfloat16 g_q_h[4194304], g_q_l[4194304];
__device__ __nv_bfloat16 g_k_h[4194304], g_k_l[4194304];
__device__ __nv_bfloat16 g_v_h[4194304], g_v_l[4194304];
// attention output [b*t][c] bf16 hi/lo (input to proj GEMM)
__device__ __nv_bfloat16 g_ao_h[4194304], g_ao_l[4194304];

// bf16 hi/lo splits of GEMM inputs
__device__ __nv_bfloat16 g_x_h[4194304],  g_x_l[4194304];   // x   [4096,1024]
__device__ __nv_bfloat16 g_w1_h[3145728], g_w1_l[3145728];  // qkv_w [3072,1024]
__device__ __nv_bfloat16 g_w2_h[1048576], g_w2_l[1048576];  // proj_w [1024,1024]

// ---------------------------------------------------------------------------
// helpers
// ---------------------------------------------------------------------------
__device__ __forceinline__ uint32_t smem_u32(const void* p) {
    uint32_t a;
    asm("{ .reg .u64 t; cvta.to.shared.u64 t, %1; cvt.u32.u64 %0, t; }" : "=r"(a) : "l"(p));
    return a;
}
__device__ __forceinline__ uint32_t swz(uint32_t off) {     // 128B rows
    return off ^ ((off >> 3) & 0x70);
}
__device__ __forceinline__ uint32_t swz256(uint32_t off) {  // 256B rows
    return off ^ ((off >> 4) & 0x70);
}
__device__ __forceinline__ void ldmx4(uint32_t* r, uint32_t addr) {
    asm volatile("ldmatrix.sync.aligned.m8n8.x4.shared.b16 {%0,%1,%2,%3}, [%4];"
                 : "=r"(r[0]), "=r"(r[1]), "=r"(r[2]), "=r"(r[3]) : "r"(addr));
}
__device__ __forceinline__ void mma_bf16(float* c, const uint32_t* a, uint32_t b0, uint32_t b1) {
    asm volatile("mma.sync.aligned.m16n8k16.row.col.f32.bf16.bf16.f32 "
                 "{%0,%1,%2,%3}, {%4,%5,%6,%7}, {%8,%9}, {%0,%1,%2,%3};"
                 : "+f"(c[0]), "+f"(c[1]), "+f"(c[2]), "+f"(c[3])
                 : "r"(a[0]), "r"(a[1]), "r"(a[2]), "r"(a[3]), "r"(b0), "r"(b1));
}

// fast 2^y via FMA only (no MUFU): magic-number round + deg-5 Taylor on [-.5,.5]
__device__ __forceinline__ float fexp2(float y) {
    y = fminf(fmaxf(y, -120.f), 80.f);
    float z = y + 12582912.f;                 // 1.5*2^23
    int iz = __float_as_int(z);
    float f = y - (z - 12582912.f);           // f in [-0.5, 0.5]
    float p = 1.3333558e-3f;                  // ln2^5/120
    p = fmaf(p, f, 9.6181291e-3f);            // ln2^4/24
    p = fmaf(p, f, 5.5504109e-2f);            // ln2^3/6
    p = fmaf(p, f, 2.4022651e-1f);            // ln2^2/2
    p = fmaf(p, f, 6.9314718e-1f);            // ln2
    p = fmaf(p, f, 1.0f);
    return p * __int_as_float((iz + (127 - 0x4B400000)) << 23);
}

// split pair -> packed bf16x2 hi (ret) and lo (out param)
__device__ __forceinline__ uint32_t pack_hl(float x, float y, uint32_t& lo) {
    __nv_bfloat16 hx = __float2bfloat16(x), hy = __float2bfloat16(y);
    __nv_bfloat16 lx = __float2bfloat16(x - __bfloat162float(hx));
    __nv_bfloat16 ly = __float2bfloat16(y - __bfloat162float(hy));
    lo = ((uint32_t)__bfloat16_as_ushort(ly) << 16) | (uint32_t)__bfloat16_as_ushort(lx);
    return ((uint32_t)__bfloat16_as_ushort(hy) << 16) | (uint32_t)__bfloat16_as_ushort(hx);
}

// ---------------------------------------------------------------------------
__global__ void split_bf16(const float* __restrict__ src, __nv_bfloat16* __restrict__ hi,
                           __nv_bfloat16* __restrict__ lo, int n4) {
    int i = blockIdx.x * blockDim.x + threadIdx.x;
    if (i < n4) {
        float4 v = ((const float4*)src)[i];
        __nv_bfloat16 h0 = __float2bfloat16(v.x), h1 = __float2bfloat16(v.y);
        __nv_bfloat16 h2 = __float2bfloat16(v.z), h3 = __float2bfloat16(v.w);
        __nv_bfloat162* H = (__nv_bfloat162*)hi;
        __nv_bfloat162* L = (__nv_bfloat162*)lo;
        H[i * 2]     = __nv_bfloat162(h0, h1);
        H[i * 2 + 1] = __nv_bfloat162(h2, h3);
        L[i * 2]     = __nv_bfloat162(__float2bfloat16(v.x - __bfloat162float(h0)),
                                      __float2bfloat16(v.y - __bfloat162float(h1)));
        L[i * 2 + 1] = __nv_bfloat162(__float2bfloat16(v.z - __bfloat162float(h2)),
                                      __float2bfloat16(v.w - __bfloat162float(h3)));
    }
}

__global__ void decay_kernel(const float* __restrict__ lambda_raw) {
    int idx = blockIdx.x * blockDim.x + threadIdx.x;
    if (idx < HH * TT) {
        int h = idx / TT;
        int d = idx % TT;
        float lam = log1pf(expf(lambda_raw[h]));
        g_decay[idx] = expf(-lam * (float)d);
    }
}

// ---------------------------------------------------------------------------
// bf16x3 mma.sync NT GEMM (as round 3), EPI 0 now emits Q/K/V^T bf16 planes.
// ---------------------------------------------------------------------------
#define OFF_AH 0
#define OFF_AL 16384
#define OFF_BH 32768
#define OFF_BL 49152
#define GEMM_SMEM 65536

__device__ __forceinline__ void load_tile_k1024(const __nv_bfloat16* __restrict__ g,
                                                char* sm, int tid) {
#pragma unroll
    for (int i = 0; i < 4; i++) {
        int slot = tid + i * 256;
        int row = slot >> 3;
        int c16 = slot & 7;
        uint4 v = *(const uint4*)(g + (size_t)row * 1024 + c16 * 8);
        *(uint4*)(sm + swz(row * 128 + c16 * 16)) = v;
    }
}

template <int EPI>
__launch_bounds__(256)
__global__ void gemm_mma(const __nv_bfloat16* __restrict__ Ah, const __nv_bfloat16* __restrict__ Al,
                         const __nv_bfloat16* __restrict__ Bh, const __nv_bfloat16* __restrict__ Bl,
                         const float* __restrict__ bias, float* __restrict__ Cout, int N) {
    extern __shared__ char smem[];
    const int tid = threadIdx.x;
    const int wid = tid >> 5;
    const int lane = tid & 31;
    const int wm = wid & 3;
    const int wn = wid >> 2;
    const int n0 = blockIdx.x * 128;
    const int m0 = blockIdx.y * 128;

    const uint32_t sAh = smem_u32(smem + OFF_AH);
    const uint32_t sAl = smem_u32(smem + OFF_AL);
    const uint32_t sBh = smem_u32(smem + OFF_BH);
    const uint32_t sBl = smem_u32(smem + OFF_BL);

    const int a_row = (lane & 7) + ((lane >> 3) & 1) * 8;
    const int a_kc  = lane >> 4;
    const int b_row = ((lane >> 4) * 8) + (lane & 7);
    const int b_kc  = (lane >> 3) & 1;

    float acc[2][8][4];
#pragma unroll
    for (int i = 0; i < 2; i++)
#pragma unroll
        for (int j = 0; j < 8; j++)
#pragma unroll
            for (int q = 0; q < 4; q++) acc[i][j][q] = 0.f;

    for (int c = 0; c < 16; c++) {
        const size_t ka = (size_t)c * 64;
        __syncthreads();
        load_tile_k1024(Ah + (size_t)m0 * 1024 + ka, smem + OFF_AH, tid);
        load_tile_k1024(Al + (size_t)m0 * 1024 + ka, smem + OFF_AL, tid);
        load_tile_k1024(Bh + (size_t)n0 * 1024 + ka, smem + OFF_BH, tid);
        load_tile_k1024(Bl + (size_t)n0 * 1024 + ka, smem + OFF_BL, tid);
        __syncthreads();

#pragma unroll
        for (int ks = 0; ks < 4; ks++) {
            uint32_t ah[2][4], al[2][4];
#pragma unroll
            for (int mi = 0; mi < 2; mi++) {
                uint32_t off = swz((wm * 32 + mi * 16 + a_row) * 128 + (ks * 2 + a_kc) * 16);
                ldmx4(ah[mi], sAh + off);
                ldmx4(al[mi], sAl + off);
            }
#pragma unroll
            for (int ng = 0; ng < 4; ng++) {
                uint32_t bh[4], bl[4];
                uint32_t off = swz((wn * 64 + ng * 16 + b_row) * 128 + (ks * 2 + b_kc) * 16);
                ldmx4(bh, sBh + off);
                ldmx4(bl, sBl + off);
#pragma unroll
                for (int mi = 0; mi < 2; mi++) {
                    mma_bf16(acc[mi][2 * ng],     ah[mi], bh[0], bh[1]);
                    mma_bf16(acc[mi][2 * ng],     al[mi], bh[0], bh[1]);
                    mma_bf16(acc[mi][2 * ng],     ah[mi], bl[0], bl[1]);
                    mma_bf16(acc[mi][2 * ng + 1], ah[mi], bh[2], bh[3]);
                    mma_bf16(acc[mi][2 * ng + 1], al[mi], bh[2], bh[3]);
                    mma_bf16(acc[mi][2 * ng + 1], ah[mi], bl[2], bl[3]);
                }
            }
        }
    }

#pragma unroll
    for (int mi = 0; mi < 2; mi++) {
#pragma unroll
        for (int j = 0; j < 8; j++) {
            int row = m0 + wm * 32 + mi * 16 + (lane >> 2);
            int o = n0 + wn * 64 + j * 8 + (lane & 3) * 2;
            float b0 = bias[o], b1 = bias[o + 1];
#pragma unroll
            for (int half = 0; half < 2; half++) {
                int m = row + half * 8;
                float vx = acc[mi][j][half * 2] + b0;
                float vy = acc[mi][j][half * 2 + 1] + b1;
                if (EPI == 0) {
                    int s = o >> 10;
                    int rem = o & 1023;
                    int hh = rem >> 6;
                    int d = rem & 63;
                    int bb = m >> 11;
                    int t = m & 2047;
                    __nv_bfloat16 h0 = __float2bfloat16(vx);
                    __nv_bfloat16 l0 = __float2bfloat16(vx - __bfloat162float(h0));
                    __nv_bfloat16 h1 = __float2bfloat16(vy);
                    __nv_bfloat16 l1 = __float2bfloat16(vy - __bfloat162float(h1));
                    if (s == 2) {
                        size_t vi = ((size_t)(bb * HH + hh) * DH + d) * TT + t;
                        g_v_h[vi] = h0;      g_v_l[vi] = l0;
                        g_v_h[vi + TT] = h1; g_v_l[vi + TT] = l1;
                    } else {
                        size_t idx = (((size_t)(bb * HH + hh) * TT + t) * DH + d) >> 1;
                        __nv_bfloat162 hv(h0, h1), lv(l0, l1);
                        if (s == 0) { ((__nv_bfloat162*)g_q_h)[idx] = hv;
                                      ((__nv_bfloat162*)g_q_l)[idx] = lv; }
                        else        { ((__nv_bfloat162*)g_k_h)[idx] = hv;
                                      ((__nv_bfloat162*)g_k_l)[idx] = lv; }
                    }
                } else {
                    *(float2*)&Cout[(size_t)m * N + o] = make_float2(vx, vy);
                }
            }
        }
    }
}

// ---------------------------------------------------------------------------
// Flash attention: mma.sync bf16x3, FMA fast-exp, no running max.
// Grid (16, 32), 256 threads. Warp w owns q-rows w*16..w*16+15.
// smem: Kh 0 | Kl 16K | Vh 32K | Vl 48K  (64 KB)
// ---------------------------------------------------------------------------
#define FL_SKH 0
#define FL_SKL 16384
#define FL_SVH 32768
#define FL_SVL 49152
#define FL_SMEM 65536

__device__ __forceinline__ void load_qk_tile(const __nv_bfloat16* __restrict__ g,
                                             char* sm, int tid) {
    // 128 rows x 64 bf16 (row stride 64 elems)
#pragma unroll
    for (int i = 0; i < 4; i++) {
        int slot = tid + i * 256;
        int row = slot >> 3;
        int c16 = slot & 7;
        uint4 v = *(const uint4*)(g + (size_t)row * 64 + c16 * 8);
        *(uint4*)(sm + swz(row * 128 + c16 * 16)) = v;
    }
}
__device__ __forceinline__ void load_vt_tile(const __nv_bfloat16* __restrict__ g,
                                             char* sm, int tid) {
    // 64 rows(d) x 128 bf16(t), gmem row stride 2048 elems
#pragma unroll
    for (int i = 0; i < 4; i++) {
        int slot = tid + i * 256;
        int row = slot >> 4;
        int c16 = slot & 15;
        uint4 v = *(const uint4*)(g + (size_t)row * 2048 + c16 * 8);
        *(uint4*)(sm + swz256(row * 256 + c16 * 16)) = v;
    }
}

__launch_bounds__(256, 1)
__global__ void flash_mma() {
    extern __shared__ char fsm[];
    const int tid = threadIdx.x;
    const int wid = tid >> 5;
    const int lane = tid & 31;
    const int b = blockIdx.y >> 4;
    const int h = blockIdx.y & 15;
    const int i0 = blockIdx.x * 128;

    const int a_row = (lane & 7) + ((lane >> 3) & 1) * 8;
    const int a_kc  = lane >> 4;
    const int b_row = ((lane >> 4) * 8) + (lane & 7);
    const int b_kc  = (lane >> 3) & 1;

    const size_t qoff = (size_t)(b * HH + h) * TT * DH;
    const __nv_bfloat16* Qh = g_q_h + qoff + (size_t)i0 * DH;
    const __nv_bfloat16* Ql = g_q_l + qoff + (size_t)i0 * DH;
    const __nv_bfloat16* Kh = g_k_h + qoff;
    const __nv_bfloat16* Kl = g_k_l + qoff;
    const __nv_bfloat16* Vh = g_v_h + qoff;   // [d][t] layout, same plane offset
    const __nv_bfloat16* Vl = g_v_l + qoff;
    const float* dec = g_decay + h * TT;

    const uint32_t sKh = smem_u32(fsm + FL_SKH);
    const uint32_t sKl = smem_u32(fsm + FL_SKL);
    const uint32_t sVh = smem_u32(fsm + FL_SVH);
    const uint32_t sVl = smem_u32(fsm + FL_SVL);

    // Prologue: Q fragments cached in registers
    load_qk_tile(Qh, fsm + FL_SKH, tid);
    load_qk_tile(Ql, fsm + FL_SKL, tid);
    __syncthreads();
    uint32_t qh[4][4], ql[4][4];
#pragma unroll
    for (int kt = 0; kt < 4; kt++) {
        uint32_t off = swz((wid * 16 + a_row) * 128 + (kt * 2 + a_kc) * 16);
        ldmx4(qh[kt], sKh + off);
        ldmx4(ql[kt], sKl + off);
    }
    __syncthreads();

    float O[8][4];
#pragma unroll
    for (int j = 0; j < 8; j++)
#pragma unroll
        for (int q = 0; q < 4; q++) O[j][q] = 0.f;
    float lsum0 = 0.f, lsum1 = 0.f;
    const float K1 = 0.125f * 1.44269504f;    // scale * log2(e)
    const int r_lo = i0 + wid * 16 + (lane >> 2);

    for (int j0 = 0; j0 < TT; j0 += 128) {
        load_qk_tile(Kh + (size_t)j0 * DH, fsm + FL_SKH, tid);
        load_qk_tile(Kl + (size_t)j0 * DH, fsm + FL_SKL, tid);
        load_vt_tile(Vh + j0, fsm + FL_SVH, tid);
        load_vt_tile(Vl + j0, fsm + FL_SVL, tid);
        __syncthreads();

        // S = Q K^T (bf16x3)
        float s[16][4];
#pragma unroll
        for (int j = 0; j < 16; j++)
#pragma unroll
            for (int q = 0; q < 4; q++) s[j][q] = 0.f;
#pragma unroll
        for (int kt = 0; kt < 4; kt++) {
#pragma unroll
            for (int ng = 0; ng < 8; ng++) {
                uint32_t kb[4], kc[4];
                uint32_t off = swz((ng * 16 + b_row) * 128 + (kt * 2 + b_kc) * 16);
                ldmx4(kb, sKh + off);
                ldmx4(kc, sKl + off);
                mma_bf16(s[2 * ng],     qh[kt], kb[0], kb[1]);
                mma_bf16(s[2 * ng],     ql[kt], kb[0], kb[1]);
                mma_bf16(s[2 * ng],     qh[kt], kc[0], kc[1]);
                mma_bf16(s[2 * ng + 1], qh[kt], kb[2], kb[3]);
                mma_bf16(s[2 * ng + 1], ql[kt], kb[2], kb[3]);
                mma_bf16(s[2 * ng + 1], qh[kt], kc[2], kc[3]);
            }
        }

        // p = exp(s * scale * decay) via FMA-only exp2 (shift-invariant softmax)
#pragma unroll
        for (int j = 0; j < 16; j++) {
            int cbase = j0 + j * 8 + (lane & 3) * 2;
#pragma unroll
            for (int c = 0; c < 4; c++) {
                int rg = r_lo + ((c >= 2) ? 8 : 0);
                int cg = cbase + (c & 1);
                float dcy = __ldg(&dec[abs(rg - cg)]);
                float p = fexp2(s[j][c] * dcy * K1);
                s[j][c] = p;
                if (c < 2) lsum0 += p; else lsum1 += p;
            }
        }

        // O += P V (bf16x3; P from registers)
#pragma unroll
        for (int kt = 0; kt < 8; kt++) {
            uint32_t ph[4], pl[4];
            ph[0] = pack_hl(s[2 * kt][0],     s[2 * kt][1],     pl[0]);
            ph[1] = pack_hl(s[2 * kt][2],     s[2 * kt][3],     pl[1]);
            ph[2] = pack_hl(s[2 * kt + 1][0], s[2 * kt + 1][1], pl[2]);
            ph[3] = pack_hl(s[2 * kt + 1][2], s[2 * kt + 1][3], pl[3]);
#pragma unroll
            for (int ng = 0; ng < 4; ng++) {
                uint32_t vh2[4], vl2[4];
                uint32_t off = swz256((ng * 16 + b_row) * 256 + (kt * 2 + b_kc) * 16);
                ldmx4(vh2, sVh + off);
                ldmx4(vl2, sVl + off);
                mma_bf16(O[2 * ng],     ph, vh2[0], vh2[1]);
                mma_bf16(O[2 * ng],     pl, vh2[0], vh2[1]);
                mma_bf16(O[2 * ng],     ph, vl2[0], vl2[1]);
                mma_bf16(O[2 * ng + 1], ph, vh2[2], vh2[3]);
                mma_bf16(O[2 * ng + 1], pl, vh2[2], vh2[3]);
                mma_bf16(O[2 * ng + 1], ph, vl2[2], vl2[3]);
            }
        }
        __syncthreads();
    }

    // quad-reduce row sums (lanes 0..3 of each quad share a row)
    lsum0 += __shfl_xor_sync(0xffffffffu, lsum0, 1);
    lsum0 += __shfl_xor_sync(0xffffffffu, lsum0, 2);
    lsum1 += __shfl_xor_sync(0xffffffffu, lsum1, 1);
    lsum1 += __shfl_xor_sync(0xffffffffu, lsum1, 2);
    const float inv0 = 1.f / lsum0;
    const float inv1 = 1.f / lsum1;

    // write attn_out bf16 hi/lo: [b*T + row][h*64 + d]
#pragma unroll
    for (int j = 0; j < 8; j++) {
        int d = j * 8 + (lane & 3) * 2;
        size_t base0 = ((size_t)b * TT + (size_t)(r_lo)) * CC + h * DH + d;
        size_t base1 = base0 + 8 * CC;
        uint32_t lo;
        uint32_t hi = pack_hl(O[j][0] * inv0, O[j][1] * inv0, lo);
        ((uint32_t*)g_ao_h)[base0 >> 1] = hi;
        ((uint32_t*)g_ao_l)[base0 >> 1] = lo;
        hi = pack_hl(O[j][2] * inv1, O[j][3] * inv1, lo);
        ((uint32_t*)g_ao_h)[base1 >> 1] = hi;
        ((uint32_t*)g_ao_l)[base1 >> 1] = lo;
    }
}

// ---------------------------------------------------------------------------
extern "C" void kernel_launch(void* const* d_in, const int* in_sizes, int n_in,
                              void* d_out, int out_size) {
    const float* x = (const float*)d_in[0];
    const float* qkv_w = (const float*)d_in[1];
    const float* qkv_b = (const float*)d_in[2];
    const float* proj_w = (const float*)d_in[3];
    const float* proj_b = (const float*)d_in[4];
    const float* lambda_raw = (const float*)d_in[5];
    float* out = (float*)d_out;

    void *p_xh, *p_xl, *p_w1h, *p_w1l, *p_w2h, *p_w2l, *p_aoh, *p_aol;
    cudaGetSymbolAddress(&p_xh, g_x_h);   cudaGetSymbolAddress(&p_xl, g_x_l);
    cudaGetSymbolAddress(&p_w1h, g_w1_h); cudaGetSymbolAddress(&p_w1l, g_w1_l);
    cudaGetSymbolAddress(&p_w2h, g_w2_h); cudaGetSymbolAddress(&p_w2l, g_w2_l);
    cudaGetSymbolAddress(&p_aoh, g_ao_h); cudaGetSymbolAddress(&p_aol, g_ao_l);

    cudaFuncSetAttribute(flash_mma, cudaFuncAttributeMaxDynamicSharedMemorySize, FL_SMEM);
    cudaFuncSetAttribute(gemm_mma<0>, cudaFuncAttributeMaxDynamicSharedMemorySize, GEMM_SMEM);
    cudaFuncSetAttribute(gemm_mma<1>, cudaFuncAttributeMaxDynamicSharedMemorySize, GEMM_SMEM);

    decay_kernel<<<(HH * TT + 255) / 256, 256>>>(lambda_raw);

    split_bf16<<<4194304 / 4 / 256, 256>>>(x, (__nv_bfloat16*)p_xh, (__nv_bfloat16*)p_xl,
                                           4194304 / 4);
    split_bf16<<<3145728 / 4 / 256, 256>>>(qkv_w, (__nv_bfloat16*)p_w1h, (__nv_bfloat16*)p_w1l,
                                           3145728 / 4);
    split_bf16<<<1048576 / 4 / 256, 256>>>(proj_w, (__nv_bfloat16*)p_w2h, (__nv_bfloat16*)p_w2l,
                                           1048576 / 4);

    // QKV: M=4096, N=3072, K=1024 -> bf16 hi/lo Q/K + V^T planes
    gemm_mma<0><<<dim3(3072 / 128, 4096 / 128), 256, GEMM_SMEM>>>(
        (const __nv_bfloat16*)p_xh, (const __nv_bfloat16*)p_xl,
        (const __nv_bfloat16*)p_w1h, (const __nv_bfloat16*)p_w1l, qkv_b, nullptr, 3072);

    flash_mma<<<dim3(TT / 128, BB * HH), 256, FL_SMEM>>>();

    // Proj: M=4096, N=1024, K=1024 (consumes g_ao hi/lo directly)
    gemm_mma<1><<<dim3(1024 / 128, 4096 / 128), 256, GEMM_SMEM>>>(
        (const __nv_bfloat16*)p_aoh, (const __nv_bfloat16*)p_aol,
        (const __nv_bfloat16*)p_w2h, (const __nv_bfloat16*)p_w2l, proj_b, out, 1024);
}

// round 5
// speedup vs baseline: 2.9134x; 1.1883x over previous
#include <cuda_runtime.h>
#include <cuda_bf16.h>
#include <math.h>
#include <stdint.h>

#define BB 2
#define TT 2048
#define CC 1024
#define HH 16
#define DH 64

// ---------------------------------------------------------------------------
// Scratch (device globals: allocation-free rule)
// ---------------------------------------------------------------------------
__device__ float g_decay[HH * TT];                 // [h][dist]

__device__ __nv_bfloat16 g_q_h[4194304], g_q_l[4194304];
__device__ __nv_bfloat16 g_k_h[4194304], g_k_l[4194304];
__device__ __nv_bfloat16 g_v_h[4194304], g_v_l[4194304];   // V^T [b][h][d][t]
__device__ __nv_bfloat16 g_ao_h[4194304], g_ao_l[4194304];

__device__ __nv_bfloat16 g_x_h[4194304],  g_x_l[4194304];
__device__ __nv_bfloat16 g_w1_h[3145728], g_w1_l[3145728];
__device__ __nv_bfloat16 g_w2_h[1048576], g_w2_l[1048576];

// ---------------------------------------------------------------------------
// helpers
// ---------------------------------------------------------------------------
__device__ __forceinline__ uint32_t smem_u32(const void* p) {
    uint32_t a;
    asm("{ .reg .u64 t; cvta.to.shared.u64 t, %1; cvt.u32.u64 %0, t; }" : "=r"(a) : "l"(p));
    return a;
}
__device__ __forceinline__ uint32_t swz(uint32_t off) {     // 128B rows
    return off ^ ((off >> 3) & 0x70);
}
__device__ __forceinline__ uint32_t swz256(uint32_t off) {  // 256B rows
    return off ^ ((off >> 4) & 0x70);
}
__device__ __forceinline__ void ldmx4(uint32_t* r, uint32_t addr) {
    asm volatile("ldmatrix.sync.aligned.m8n8.x4.shared.b16 {%0,%1,%2,%3}, [%4];"
                 : "=r"(r[0]), "=r"(r[1]), "=r"(r[2]), "=r"(r[3]) : "r"(addr));
}
__device__ __forceinline__ void mma_bf16(float* c, const uint32_t* a, uint32_t b0, uint32_t b1) {
    asm volatile("mma.sync.aligned.m16n8k16.row.col.f32.bf16.bf16.f32 "
                 "{%0,%1,%2,%3}, {%4,%5,%6,%7}, {%8,%9}, {%0,%1,%2,%3};"
                 : "+f"(c[0]), "+f"(c[1]), "+f"(c[2]), "+f"(c[3])
                 : "r"(a[0]), "r"(a[1]), "r"(a[2]), "r"(a[3]), "r"(b0), "r"(b1));
}
__device__ __forceinline__ void cpa16(uint32_t dst, const void* src) {
    asm volatile("cp.async.cg.shared.global [%0], [%1], 16;" :: "r"(dst), "l"(src));
}
#define CP_COMMIT() asm volatile("cp.async.commit_group;" ::: "memory")
#define CP_WAIT1()  asm volatile("cp.async.wait_group 1;" ::: "memory")
#define CP_WAIT0()  asm volatile("cp.async.wait_group 0;" ::: "memory")

// fast 2^y via FMA only (no MUFU)
__device__ __forceinline__ float fexp2(float y) {
    y = fminf(fmaxf(y, -120.f), 80.f);
    float z = y + 12582912.f;
    int iz = __float_as_int(z);
    float f = y - (z - 12582912.f);
    float p = 1.3333558e-3f;
    p = fmaf(p, f, 9.6181291e-3f);
    p = fmaf(p, f, 5.5504109e-2f);
    p = fmaf(p, f, 2.4022651e-1f);
    p = fmaf(p, f, 6.9314718e-1f);
    p = fmaf(p, f, 1.0f);
    return p * __int_as_float((iz + (127 - 0x4B400000)) << 23);
}
__device__ __forceinline__ uint32_t pack_hl(float x, float y, uint32_t& lo) {
    __nv_bfloat16 hx = __float2bfloat16(x), hy = __float2bfloat16(y);
    __nv_bfloat16 lx = __float2bfloat16(x - __bfloat162float(hx));
    __nv_bfloat16 ly = __float2bfloat16(y - __bfloat162float(hy));
    lo = ((uint32_t)__bfloat16_as_ushort(ly) << 16) | (uint32_t)__bfloat16_as_ushort(lx);
    return ((uint32_t)__bfloat16_as_ushort(hy) << 16) | (uint32_t)__bfloat16_as_ushort(hx);
}

// ---------------------------------------------------------------------------
__global__ void split_bf16(const float* __restrict__ src, __nv_bfloat16* __restrict__ hi,
                           __nv_bfloat16* __restrict__ lo, int n4) {
    int i = blockIdx.x * blockDim.x + threadIdx.x;
    if (i < n4) {
        float4 v = ((const float4*)src)[i];
        __nv_bfloat16 h0 = __float2bfloat16(v.x), h1 = __float2bfloat16(v.y);
        __nv_bfloat16 h2 = __float2bfloat16(v.z), h3 = __float2bfloat16(v.w);
        __nv_bfloat162* H = (__nv_bfloat162*)hi;
        __nv_bfloat162* L = (__nv_bfloat162*)lo;
        H[i * 2]     = __nv_bfloat162(h0, h1);
        H[i * 2 + 1] = __nv_bfloat162(h2, h3);
        L[i * 2]     = __nv_bfloat162(__float2bfloat16(v.x - __bfloat162float(h0)),
                                      __float2bfloat16(v.y - __bfloat162float(h1)));
        L[i * 2 + 1] = __nv_bfloat162(__float2bfloat16(v.z - __bfloat162float(h2)),
                                      __float2bfloat16(v.w - __bfloat162float(h3)));
    }
}

__global__ void decay_kernel(const float* __restrict__ lambda_raw) {
    int idx = blockIdx.x * blockDim.x + threadIdx.x;
    if (idx < HH * TT) {
        int h = idx / TT;
        int d = idx % TT;
        float lam = log1pf(expf(lambda_raw[h]));
        g_decay[idx] = expf(-lam * (float)d);
    }
}

// ---------------------------------------------------------------------------
// async tile loaders (128B-row and 256B-row variants)
// ---------------------------------------------------------------------------
__device__ __forceinline__ void gload_k1024(const __nv_bfloat16* __restrict__ g,
                                            uint32_t dst, int tid) {
    // 128 rows x 64 bf16, gmem row stride 1024 elems
#pragma unroll
    for (int i = 0; i < 4; i++) {
        int slot = tid + i * 256;
        int row = slot >> 3;
        int c16 = slot & 7;
        cpa16(dst + swz(row * 128 + c16 * 16), g + (size_t)row * 1024 + c16 * 8);
    }
}
__device__ __forceinline__ void gload_qk(const __nv_bfloat16* __restrict__ g,
                                         uint32_t dst, int tid) {
    // 128 rows x 64 bf16, gmem row stride 64 elems (contiguous 16KB)
#pragma unroll
    for (int i = 0; i < 4; i++) {
        int slot = tid + i * 256;
        int row = slot >> 3;
        int c16 = slot & 7;
        cpa16(dst + swz(row * 128 + c16 * 16), g + (size_t)row * 64 + c16 * 8);
    }
}
__device__ __forceinline__ void gload_vt(const __nv_bfloat16* __restrict__ g,
                                         uint32_t dst, int tid) {
    // 64 rows(d) x 128 bf16(t), gmem row stride 2048 elems
#pragma unroll
    for (int i = 0; i < 4; i++) {
        int slot = tid + i * 256;
        int row = slot >> 4;
        int c16 = slot & 15;
        cpa16(dst + swz256(row * 256 + c16 * 16), g + (size_t)row * 2048 + c16 * 8);
    }
}

// ---------------------------------------------------------------------------
// bf16x3 mma.sync NT GEMM, cp.async double-buffered.
// smem: 2 x (AH|AL|BH|BL) 16KB each = 128KB
// ---------------------------------------------------------------------------
#define OFF_AH 0
#define OFF_AL 16384
#define OFF_BH 32768
#define OFF_BL 49152
#define GBUF   65536
#define GEMM_SMEM 131072

template <int EPI>
__launch_bounds__(256)
__global__ void gemm_mma(const __nv_bfloat16* __restrict__ Ah, const __nv_bfloat16* __restrict__ Al,
                         const __nv_bfloat16* __restrict__ Bh, const __nv_bfloat16* __restrict__ Bl,
                         const float* __restrict__ bias, float* __restrict__ Cout, int N) {
    extern __shared__ char smem[];
    const uint32_t sb = smem_u32(smem);
    const int tid = threadIdx.x;
    const int wid = tid >> 5;
    const int lane = tid & 31;
    const int wm = wid & 3;
    const int wn = wid >> 2;
    const int n0 = blockIdx.x * 128;
    const int m0 = blockIdx.y * 128;

    const int a_row = (lane & 7) + ((lane >> 3) & 1) * 8;
    const int a_kc  = lane >> 4;
    const int b_row = ((lane >> 4) * 8) + (lane & 7);
    const int b_kc  = (lane >> 3) & 1;

    const __nv_bfloat16* Abase_h = Ah + (size_t)m0 * 1024;
    const __nv_bfloat16* Abase_l = Al + (size_t)m0 * 1024;
    const __nv_bfloat16* Bbase_h = Bh + (size_t)n0 * 1024;
    const __nv_bfloat16* Bbase_l = Bl + (size_t)n0 * 1024;

    float acc[2][8][4];
#pragma unroll
    for (int i = 0; i < 2; i++)
#pragma unroll
        for (int j = 0; j < 8; j++)
#pragma unroll
            for (int q = 0; q < 4; q++) acc[i][j][q] = 0.f;

    // prefetch chunk 0 -> buf 0
    gload_k1024(Abase_h, sb + OFF_AH, tid);
    gload_k1024(Abase_l, sb + OFF_AL, tid);
    gload_k1024(Bbase_h, sb + OFF_BH, tid);
    gload_k1024(Bbase_l, sb + OFF_BL, tid);
    CP_COMMIT();

    for (int c = 0; c < 16; c++) {
        const uint32_t cur = (c & 1) ? GBUF : 0u;
        const uint32_t nxt = cur ^ GBUF;
        if (c < 15) {
            const size_t ka = (size_t)(c + 1) * 64;
            gload_k1024(Abase_h + ka, sb + nxt + OFF_AH, tid);
            gload_k1024(Abase_l + ka, sb + nxt + OFF_AL, tid);
            gload_k1024(Bbase_h + ka, sb + nxt + OFF_BH, tid);
            gload_k1024(Bbase_l + ka, sb + nxt + OFF_BL, tid);
            CP_COMMIT();
            CP_WAIT1();
        } else {
            CP_WAIT0();
        }
        __syncthreads();

        const uint32_t sAh = sb + cur + OFF_AH, sAl = sb + cur + OFF_AL;
        const uint32_t sBh = sb + cur + OFF_BH, sBl = sb + cur + OFF_BL;
#pragma unroll
        for (int ks = 0; ks < 4; ks++) {
            uint32_t ah[2][4], al[2][4];
#pragma unroll
            for (int mi = 0; mi < 2; mi++) {
                uint32_t off = swz((wm * 32 + mi * 16 + a_row) * 128 + (ks * 2 + a_kc) * 16);
                ldmx4(ah[mi], sAh + off);
                ldmx4(al[mi], sAl + off);
            }
#pragma unroll
            for (int ng = 0; ng < 4; ng++) {
                uint32_t bh[4], bl[4];
                uint32_t off = swz((wn * 64 + ng * 16 + b_row) * 128 + (ks * 2 + b_kc) * 16);
                ldmx4(bh, sBh + off);
                ldmx4(bl, sBl + off);
#pragma unroll
                for (int mi = 0; mi < 2; mi++) {
                    mma_bf16(acc[mi][2 * ng],     ah[mi], bh[0], bh[1]);
                    mma_bf16(acc[mi][2 * ng],     al[mi], bh[0], bh[1]);
                    mma_bf16(acc[mi][2 * ng],     ah[mi], bl[0], bl[1]);
                    mma_bf16(acc[mi][2 * ng + 1], ah[mi], bh[2], bh[3]);
                    mma_bf16(acc[mi][2 * ng + 1], al[mi], bh[2], bh[3]);
                    mma_bf16(acc[mi][2 * ng + 1], ah[mi], bl[2], bl[3]);
                }
            }
        }
        __syncthreads();
    }

#pragma unroll
    for (int mi = 0; mi < 2; mi++) {
#pragma unroll
        for (int j = 0; j < 8; j++) {
            int row = m0 + wm * 32 + mi * 16 + (lane >> 2);
            int o = n0 + wn * 64 + j * 8 + (lane & 3) * 2;
            float b0 = bias[o], b1 = bias[o + 1];
#pragma unroll
            for (int half = 0; half < 2; half++) {
                int m = row + half * 8;
                float vx = acc[mi][j][half * 2] + b0;
                float vy = acc[mi][j][half * 2 + 1] + b1;
                if (EPI == 0) {
                    int s = o >> 10;
                    int rem = o & 1023;
                    int hh = rem >> 6;
                    int d = rem & 63;
                    int bb = m >> 11;
                    int t = m & 2047;
                    __nv_bfloat16 h0 = __float2bfloat16(vx);
                    __nv_bfloat16 l0 = __float2bfloat16(vx - __bfloat162float(h0));
                    __nv_bfloat16 h1 = __float2bfloat16(vy);
                    __nv_bfloat16 l1 = __float2bfloat16(vy - __bfloat162float(h1));
                    if (s == 2) {
                        size_t vi = ((size_t)(bb * HH + hh) * DH + d) * TT + t;
                        g_v_h[vi] = h0;      g_v_l[vi] = l0;
                        g_v_h[vi + TT] = h1; g_v_l[vi + TT] = l1;
                    } else {
                        size_t idx = (((size_t)(bb * HH + hh) * TT + t) * DH + d) >> 1;
                        __nv_bfloat162 hv(h0, h1), lv(l0, l1);
                        if (s == 0) { ((__nv_bfloat162*)g_q_h)[idx] = hv;
                                      ((__nv_bfloat162*)g_q_l)[idx] = lv; }
                        else        { ((__nv_bfloat162*)g_k_h)[idx] = hv;
                                      ((__nv_bfloat162*)g_k_l)[idx] = lv; }
                    }
                } else {
                    *(float2*)&Cout[(size_t)m * N + o] = make_float2(vx, vy);
                }
            }
        }
    }
}

// ---------------------------------------------------------------------------
// Flash attention: mma.sync bf16x3, FMA fast-exp, cp.async double-buffered.
// smem: 2 x (KH|KL|VH|VL) 16KB each = 128KB
// ---------------------------------------------------------------------------
#define FL_SKH 0
#define FL_SKL 16384
#define FL_SVH 32768
#define FL_SVL 49152
#define FLBUF  65536
#define FL_SMEM 131072

__launch_bounds__(256, 1)
__global__ void flash_mma() {
    extern __shared__ char fsm[];
    const uint32_t sb = smem_u32(fsm);
    const int tid = threadIdx.x;
    const int wid = tid >> 5;
    const int lane = tid & 31;
    const int b = blockIdx.y >> 4;
    const int h = blockIdx.y & 15;
    const int i0 = blockIdx.x * 128;

    const int a_row = (lane & 7) + ((lane >> 3) & 1) * 8;
    const int a_kc  = lane >> 4;
    const int b_row = ((lane >> 4) * 8) + (lane & 7);
    const int b_kc  = (lane >> 3) & 1;

    const size_t qoff = (size_t)(b * HH + h) * TT * DH;
    const __nv_bfloat16* Qh = g_q_h + qoff + (size_t)i0 * DH;
    const __nv_bfloat16* Ql = g_q_l + qoff + (size_t)i0 * DH;
    const __nv_bfloat16* Kh = g_k_h + qoff;
    const __nv_bfloat16* Kl = g_k_l + qoff;
    const __nv_bfloat16* Vh = g_v_h + qoff;
    const __nv_bfloat16* Vl = g_v_l + qoff;
    const float* dec = g_decay + h * TT;

    // group 0: Q -> buf0 (K slots); group 1: tile0 -> buf1
    gload_qk(Qh, sb + FL_SKH, tid);
    gload_qk(Ql, sb + FL_SKL, tid);
    CP_COMMIT();
    gload_qk(Kh, sb + FLBUF + FL_SKH, tid);
    gload_qk(Kl, sb + FLBUF + FL_SKL, tid);
    gload_vt(Vh, sb + FLBUF + FL_SVH, tid);
    gload_vt(Vl, sb + FLBUF + FL_SVL, tid);
    CP_COMMIT();
    CP_WAIT1();          // Q ready (tile0 may still be in flight)
    __syncthreads();

    uint32_t qh[4][4], ql[4][4];
#pragma unroll
    for (int kt = 0; kt < 4; kt++) {
        uint32_t off = swz((wid * 16 + a_row) * 128 + (kt * 2 + a_kc) * 16);
        ldmx4(qh[kt], sb + FL_SKH + off);
        ldmx4(ql[kt], sb + FL_SKL + off);
    }
    __syncthreads();     // Q reads done; buf0 free for tile1

    float O[8][4];
#pragma unroll
    for (int j = 0; j < 8; j++)
#pragma unroll
        for (int q = 0; q < 4; q++) O[j][q] = 0.f;
    float lsum0 = 0.f, lsum1 = 0.f;
    const float K1 = 0.125f * 1.44269504f;    // scale * log2(e)
    const int r_lo = i0 + wid * 16 + (lane >> 2);

    for (int c = 0; c < 16; c++) {            // tile c lives in buf[(c+1)&1]
        const uint32_t cur = (c & 1) ? 0u : FLBUF;
        const uint32_t nxt = cur ^ FLBUF;
        if (c < 15) {
            const size_t j1 = (size_t)(c + 1) * 128;
            gload_qk(Kh + j1 * DH, sb + nxt + FL_SKH, tid);
            gload_qk(Kl + j1 * DH, sb + nxt + FL_SKL, tid);
            gload_vt(Vh + j1, sb + nxt + FL_SVH, tid);
            gload_vt(Vl + j1, sb + nxt + FL_SVL, tid);
            CP_COMMIT();
            CP_WAIT1();
        } else {
            CP_WAIT0();
        }
        __syncthreads();

        const uint32_t sKh = sb + cur + FL_SKH, sKl = sb + cur + FL_SKL;
        const uint32_t sVh = sb + cur + FL_SVH, sVl = sb + cur + FL_SVL;
        const int j0 = c * 128;

        // S = Q K^T (bf16x3)
        float s[16][4];
#pragma unroll
        for (int j = 0; j < 16; j++)
#pragma unroll
            for (int q = 0; q < 4; q++) s[j][q] = 0.f;
#pragma unroll
        for (int kt = 0; kt < 4; kt++) {
#pragma unroll
            for (int ng = 0; ng < 8; ng++) {
                uint32_t kb[4], kc[4];
                uint32_t off = swz((ng * 16 + b_row) * 128 + (kt * 2 + b_kc) * 16);
                ldmx4(kb, sKh + off);
                ldmx4(kc, sKl + off);
                mma_bf16(s[2 * ng],     qh[kt], kb[0], kb[1]);
                mma_bf16(s[2 * ng],     ql[kt], kb[0], kb[1]);
                mma_bf16(s[2 * ng],     qh[kt], kc[0], kc[1]);
                mma_bf16(s[2 * ng + 1], qh[kt], kb[2], kb[3]);
                mma_bf16(s[2 * ng + 1], ql[kt], kb[2], kb[3]);
                mma_bf16(s[2 * ng + 1], qh[kt], kc[2], kc[3]);
            }
        }

        // p = exp2(s * scale*log2e * decay)
#pragma unroll
        for (int j = 0; j < 16; j++) {
            int cbase = j0 + j * 8 + (lane & 3) * 2;
#pragma unroll
            for (int cc = 0; cc < 4; cc++) {
                int rg = r_lo + ((cc >= 2) ? 8 : 0);
                int cg = cbase + (cc & 1);
                float dcy = __ldg(&dec[abs(rg - cg)]);
                float p = fexp2(s[j][cc] * dcy * K1);
                s[j][cc] = p;
                if (cc < 2) lsum0 += p; else lsum1 += p;
            }
        }

        // O += P V (bf16x3; P from registers)
#pragma unroll
        for (int kt = 0; kt < 8; kt++) {
            uint32_t ph[4], pl[4];
            ph[0] = pack_hl(s[2 * kt][0],     s[2 * kt][1],     pl[0]);
            ph[1] = pack_hl(s[2 * kt][2],     s[2 * kt][3],     pl[1]);
            ph[2] = pack_hl(s[2 * kt + 1][0], s[2 * kt + 1][1], pl[2]);
            ph[3] = pack_hl(s[2 * kt + 1][2], s[2 * kt + 1][3], pl[3]);
#pragma unroll
            for (int ng = 0; ng < 4; ng++) {
                uint32_t vh2[4], vl2[4];
                uint32_t off = swz256((ng * 16 + b_row) * 256 + (kt * 2 + b_kc) * 16);
                ldmx4(vh2, sVh + off);
                ldmx4(vl2, sVl + off);
                mma_bf16(O[2 * ng],     ph, vh2[0], vh2[1]);
                mma_bf16(O[2 * ng],     pl, vh2[0], vh2[1]);
                mma_bf16(O[2 * ng],     ph, vl2[0], vl2[1]);
                mma_bf16(O[2 * ng + 1], ph, vh2[2], vh2[3]);
                mma_bf16(O[2 * ng + 1], pl, vh2[2], vh2[3]);
                mma_bf16(O[2 * ng + 1], ph, vl2[2], vl2[3]);
            }
        }
        __syncthreads();
    }

    lsum0 += __shfl_xor_sync(0xffffffffu, lsum0, 1);
    lsum0 += __shfl_xor_sync(0xffffffffu, lsum0, 2);
    lsum1 += __shfl_xor_sync(0xffffffffu, lsum1, 1);
    lsum1 += __shfl_xor_sync(0xffffffffu, lsum1, 2);
    const float inv0 = 1.f / lsum0;
    const float inv1 = 1.f / lsum1;

#pragma unroll
    for (int j = 0; j < 8; j++) {
        int d = j * 8 + (lane & 3) * 2;
        size_t base0 = ((size_t)b * TT + (size_t)(r_lo)) * CC + h * DH + d;
        size_t base1 = base0 + 8 * CC;
        uint32_t lo;
        uint32_t hi = pack_hl(O[j][0] * inv0, O[j][1] * inv0, lo);
        ((uint32_t*)g_ao_h)[base0 >> 1] = hi;
        ((uint32_t*)g_ao_l)[base0 >> 1] = lo;
        hi = pack_hl(O[j][2] * inv1, O[j][3] * inv1, lo);
        ((uint32_t*)g_ao_h)[base1 >> 1] = hi;
        ((uint32_t*)g_ao_l)[base1 >> 1] = lo;
    }
}

// ---------------------------------------------------------------------------
extern "C" void kernel_launch(void* const* d_in, const int* in_sizes, int n_in,
                              void* d_out, int out_size) {
    const float* x = (const float*)d_in[0];
    const float* qkv_w = (const float*)d_in[1];
    const float* qkv_b = (const float*)d_in[2];
    const float* proj_w = (const float*)d_in[3];
    const float* proj_b = (const float*)d_in[4];
    const float* lambda_raw = (const float*)d_in[5];
    float* out = (float*)d_out;

    void *p_xh, *p_xl, *p_w1h, *p_w1l, *p_w2h, *p_w2l, *p_aoh, *p_aol;
    cudaGetSymbolAddress(&p_xh, g_x_h);   cudaGetSymbolAddress(&p_xl, g_x_l);
    cudaGetSymbolAddress(&p_w1h, g_w1_h); cudaGetSymbolAddress(&p_w1l, g_w1_l);
    cudaGetSymbolAddress(&p_w2h, g_w2_h); cudaGetSymbolAddress(&p_w2l, g_w2_l);
    cudaGetSymbolAddress(&p_aoh, g_ao_h); cudaGetSymbolAddress(&p_aol, g_ao_l);

    cudaFuncSetAttribute(flash_mma, cudaFuncAttributeMaxDynamicSharedMemorySize, FL_SMEM);
    cudaFuncSetAttribute(gemm_mma<0>, cudaFuncAttributeMaxDynamicSharedMemorySize, GEMM_SMEM);
    cudaFuncSetAttribute(gemm_mma<1>, cudaFuncAttributeMaxDynamicSharedMemorySize, GEMM_SMEM);

    decay_kernel<<<(HH * TT + 255) / 256, 256>>>(lambda_raw);

    split_bf16<<<4194304 / 4 / 256, 256>>>(x, (__nv_bfloat16*)p_xh, (__nv_bfloat16*)p_xl,
                                           4194304 / 4);
    split_bf16<<<3145728 / 4 / 256, 256>>>(qkv_w, (__nv_bfloat16*)p_w1h, (__nv_bfloat16*)p_w1l,
                                           3145728 / 4);
    split_bf16<<<1048576 / 4 / 256, 256>>>(proj_w, (__nv_bfloat16*)p_w2h, (__nv_bfloat16*)p_w2l,
                                           1048576 / 4);

    gemm_mma<0><<<dim3(3072 / 128, 4096 / 128), 256, GEMM_SMEM>>>(
        (const __nv_bfloat16*)p_xh, (const __nv_bfloat16*)p_xl,
        (const __nv_bfloat16*)p_w1h, (const __nv_bfloat16*)p_w1l, qkv_b, nullptr, 3072);

    flash_mma<<<dim3(TT / 128, BB * HH), 256, FL_SMEM>>>();

    gemm_mma<1><<<dim3(1024 / 128, 4096 / 128), 256, GEMM_SMEM>>>(
        (const __nv_bfloat16*)p_aoh, (const __nv_bfloat16*)p_aol,
        (const __nv_bfloat16*)p_w2h, (const __nv_bfloat16*)p_w2l, proj_b, out, 1024);
}

// round 6
// speedup vs baseline: 3.0068x; 1.0321x over previous
#include <cuda_runtime.h>
#include <cuda_bf16.h>
#include <math.h>
#include <stdint.h>

#define BB 2
#define TT 2048
#define CC 1024
#define HH 16
#define DH 64

// ---------------------------------------------------------------------------
// Scratch (device globals: allocation-free rule)
// ---------------------------------------------------------------------------
__device__ float g_decay[HH * TT];                 // [h][dist]

__device__ __nv_bfloat16 g_q_h[4194304], g_q_l[4194304];
__device__ __nv_bfloat16 g_k_h[4194304], g_k_l[4194304];
__device__ __nv_bfloat16 g_v_h[4194304], g_v_l[4194304];   // V^T [b][h][d][t]
__device__ __nv_bfloat16 g_ao_h[4194304], g_ao_l[4194304];

__device__ __nv_bfloat16 g_x_h[4194304],  g_x_l[4194304];
__device__ __nv_bfloat16 g_w1_h[3145728], g_w1_l[3145728];
__device__ __nv_bfloat16 g_w2_h[1048576], g_w2_l[1048576];

// ---------------------------------------------------------------------------
// helpers
// ---------------------------------------------------------------------------
__device__ __forceinline__ uint32_t smem_u32(const void* p) {
    uint32_t a;
    asm("{ .reg .u64 t; cvta.to.shared.u64 t, %1; cvt.u32.u64 %0, t; }" : "=r"(a) : "l"(p));
    return a;
}
__device__ __forceinline__ uint32_t swz(uint32_t off) {     // 128B rows
    return off ^ ((off >> 3) & 0x70);
}
__device__ __forceinline__ uint32_t swz256(uint32_t off) {  // 256B rows
    return off ^ ((off >> 4) & 0x70);
}
__device__ __forceinline__ void ldmx4(uint32_t* r, uint32_t addr) {
    asm volatile("ldmatrix.sync.aligned.m8n8.x4.shared.b16 {%0,%1,%2,%3}, [%4];"
                 : "=r"(r[0]), "=r"(r[1]), "=r"(r[2]), "=r"(r[3]) : "r"(addr));
}
__device__ __forceinline__ void mma_bf16(float* c, const uint32_t* a, uint32_t b0, uint32_t b1) {
    asm volatile("mma.sync.aligned.m16n8k16.row.col.f32.bf16.bf16.f32 "
                 "{%0,%1,%2,%3}, {%4,%5,%6,%7}, {%8,%9}, {%0,%1,%2,%3};"
                 : "+f"(c[0]), "+f"(c[1]), "+f"(c[2]), "+f"(c[3])
                 : "r"(a[0]), "r"(a[1]), "r"(a[2]), "r"(a[3]), "r"(b0), "r"(b1));
}
__device__ __forceinline__ void cpa16(uint32_t dst, const void* src) {
    asm volatile("cp.async.cg.shared.global [%0], [%1], 16;" :: "r"(dst), "l"(src));
}
#define CP_COMMIT() asm volatile("cp.async.commit_group;" ::: "memory")
#define CP_WAIT2()  asm volatile("cp.async.wait_group 2;" ::: "memory")
#define CP_WAIT1()  asm volatile("cp.async.wait_group 1;" ::: "memory")
#define CP_WAIT0()  asm volatile("cp.async.wait_group 0;" ::: "memory")

// fast 2^y via FMA only (no MUFU)
__device__ __forceinline__ float fexp2(float y) {
    y = fminf(fmaxf(y, -120.f), 80.f);
    float z = y + 12582912.f;
    int iz = __float_as_int(z);
    float f = y - (z - 12582912.f);
    float p = 1.3333558e-3f;
    p = fmaf(p, f, 9.6181291e-3f);
    p = fmaf(p, f, 5.5504109e-2f);
    p = fmaf(p, f, 2.4022651e-1f);
    p = fmaf(p, f, 6.9314718e-1f);
    p = fmaf(p, f, 1.0f);
    return p * __int_as_float((iz + (127 - 0x4B400000)) << 23);
}
__device__ __forceinline__ uint32_t pack_hl(float x, float y, uint32_t& lo) {
    __nv_bfloat16 hx = __float2bfloat16(x), hy = __float2bfloat16(y);
    __nv_bfloat16 lx = __float2bfloat16(x - __bfloat162float(hx));
    __nv_bfloat16 ly = __float2bfloat16(y - __bfloat162float(hy));
    lo = ((uint32_t)__bfloat16_as_ushort(ly) << 16) | (uint32_t)__bfloat16_as_ushort(lx);
    return ((uint32_t)__bfloat16_as_ushort(hy) << 16) | (uint32_t)__bfloat16_as_ushort(hx);
}

// ---------------------------------------------------------------------------
__global__ void split_bf16(const float* __restrict__ src, __nv_bfloat16* __restrict__ hi,
                           __nv_bfloat16* __restrict__ lo, int n4) {
    int i = blockIdx.x * blockDim.x + threadIdx.x;
    if (i < n4) {
        float4 v = ((const float4*)src)[i];
        __nv_bfloat16 h0 = __float2bfloat16(v.x), h1 = __float2bfloat16(v.y);
        __nv_bfloat16 h2 = __float2bfloat16(v.z), h3 = __float2bfloat16(v.w);
        __nv_bfloat162* H = (__nv_bfloat162*)hi;
        __nv_bfloat162* L = (__nv_bfloat162*)lo;
        H[i * 2]     = __nv_bfloat162(h0, h1);
        H[i * 2 + 1] = __nv_bfloat162(h2, h3);
        L[i * 2]     = __nv_bfloat162(__float2bfloat16(v.x - __bfloat162float(h0)),
                                      __float2bfloat16(v.y - __bfloat162float(h1)));
        L[i * 2 + 1] = __nv_bfloat162(__float2bfloat16(v.z - __bfloat162float(h2)),
                                      __float2bfloat16(v.w - __bfloat162float(h3)));
    }
}

__global__ void decay_kernel(const float* __restrict__ lambda_raw) {
    int idx = blockIdx.x * blockDim.x + threadIdx.x;
    if (idx < HH * TT) {
        int h = idx / TT;
        int d = idx % TT;
        float lam = log1pf(expf(lambda_raw[h]));
        g_decay[idx] = expf(-lam * (float)d);
    }
}

// ---------------------------------------------------------------------------
// async tile loaders
// ---------------------------------------------------------------------------
__device__ __forceinline__ void gload_a256(const __nv_bfloat16* __restrict__ g,
                                           uint32_t dst, int tid) {
    // 256 rows x 64 bf16, gmem row stride 1024 (32KB plane)
#pragma unroll
    for (int i = 0; i < 8; i++) {
        int slot = tid + i * 256;
        int row = slot >> 3;
        int c16 = slot & 7;
        cpa16(dst + swz(row * 128 + c16 * 16), g + (size_t)row * 1024 + c16 * 8);
    }
}
__device__ __forceinline__ void gload_b128(const __nv_bfloat16* __restrict__ g,
                                           uint32_t dst, int tid) {
    // 128 rows x 64 bf16, gmem row stride 1024 (16KB plane)
#pragma unroll
    for (int i = 0; i < 4; i++) {
        int slot = tid + i * 256;
        int row = slot >> 3;
        int c16 = slot & 7;
        cpa16(dst + swz(row * 128 + c16 * 16), g + (size_t)row * 1024 + c16 * 8);
    }
}
__device__ __forceinline__ void gload_qk(const __nv_bfloat16* __restrict__ g,
                                         uint32_t dst, int tid) {
    // 128 rows x 64 bf16, contiguous (16KB)
#pragma unroll
    for (int i = 0; i < 4; i++) {
        int slot = tid + i * 256;
        int row = slot >> 3;
        int c16 = slot & 7;
        cpa16(dst + swz(row * 128 + c16 * 16), g + (size_t)row * 64 + c16 * 8);
    }
}
__device__ __forceinline__ void gload_vt(const __nv_bfloat16* __restrict__ g,
                                         uint32_t dst, int tid) {
    // 64 rows(d) x 128 bf16(t), gmem row stride 2048
#pragma unroll
    for (int i = 0; i < 4; i++) {
        int slot = tid + i * 256;
        int row = slot >> 4;
        int c16 = slot & 15;
        cpa16(dst + swz256(row * 256 + c16 * 16), g + (size_t)row * 2048 + c16 * 8);
    }
}

// ---------------------------------------------------------------------------
// bf16x3 mma.sync NT GEMM, 256x128 CTA tile, BK=64, double-buffered.
// 8 warps as 4(m) x 2(n): warp tile 64x64.
// smem buffer: AH 32K | AL 32K | BH 16K | BL 16K = 96KB; x2 = 192KB
// ---------------------------------------------------------------------------
#define GA_H 0
#define GA_L 32768
#define GB_H 65536
#define GB_L 81920
#define GBUF 98304
#define GEMM_SMEM 196608

template <int EPI>
__launch_bounds__(256, 1)
__global__ void gemm_mma(const __nv_bfloat16* __restrict__ Ah, const __nv_bfloat16* __restrict__ Al,
                         const __nv_bfloat16* __restrict__ Bh, const __nv_bfloat16* __restrict__ Bl,
                         const float* __restrict__ bias, float* __restrict__ Cout, int N) {
    extern __shared__ char smem[];
    const uint32_t sb = smem_u32(smem);
    const int tid = threadIdx.x;
    const int wid = tid >> 5;
    const int lane = tid & 31;
    const int wm = wid & 3;        // 4 M-groups of 64 rows
    const int wn = wid >> 2;       // 2 N-groups of 64 cols
    const int n0 = blockIdx.x * 128;
    const int m0 = blockIdx.y * 256;

    const int a_row = (lane & 7) + ((lane >> 3) & 1) * 8;
    const int a_kc  = lane >> 4;
    const int b_row = ((lane >> 4) * 8) + (lane & 7);
    const int b_kc  = (lane >> 3) & 1;

    const __nv_bfloat16* Abase_h = Ah + (size_t)m0 * 1024;
    const __nv_bfloat16* Abase_l = Al + (size_t)m0 * 1024;
    const __nv_bfloat16* Bbase_h = Bh + (size_t)n0 * 1024;
    const __nv_bfloat16* Bbase_l = Bl + (size_t)n0 * 1024;

    float acc[4][8][4];
#pragma unroll
    for (int i = 0; i < 4; i++)
#pragma unroll
        for (int j = 0; j < 8; j++)
#pragma unroll
            for (int q = 0; q < 4; q++) acc[i][j][q] = 0.f;

    gload_a256(Abase_h, sb + GA_H, tid);
    gload_a256(Abase_l, sb + GA_L, tid);
    gload_b128(Bbase_h, sb + GB_H, tid);
    gload_b128(Bbase_l, sb + GB_L, tid);
    CP_COMMIT();

    for (int c = 0; c < 16; c++) {
        const uint32_t cur = (c & 1) ? GBUF : 0u;
        const uint32_t nxt = cur ^ GBUF;
        if (c < 15) {
            const size_t ka = (size_t)(c + 1) * 64;
            gload_a256(Abase_h + ka, sb + nxt + GA_H, tid);
            gload_a256(Abase_l + ka, sb + nxt + GA_L, tid);
            gload_b128(Bbase_h + ka, sb + nxt + GB_H, tid);
            gload_b128(Bbase_l + ka, sb + nxt + GB_L, tid);
            CP_COMMIT();
            CP_WAIT1();
        } else {
            CP_WAIT0();
        }
        __syncthreads();

        const uint32_t sAh = sb + cur + GA_H, sAl = sb + cur + GA_L;
        const uint32_t sBh = sb + cur + GB_H, sBl = sb + cur + GB_L;
#pragma unroll
        for (int kt = 0; kt < 4; kt++) {
            uint32_t ah[4][4], al[4][4];
#pragma unroll
            for (int mi = 0; mi < 4; mi++) {
                uint32_t off = swz((wm * 64 + mi * 16 + a_row) * 128 + (kt * 2 + a_kc) * 16);
                ldmx4(ah[mi], sAh + off);
                ldmx4(al[mi], sAl + off);
            }
#pragma unroll
            for (int ng = 0; ng < 4; ng++) {
                uint32_t bh[4], bl[4];
                uint32_t off = swz((wn * 64 + ng * 16 + b_row) * 128 + (kt * 2 + b_kc) * 16);
                ldmx4(bh, sBh + off);
                ldmx4(bl, sBl + off);
#pragma unroll
                for (int mi = 0; mi < 4; mi++) {
                    mma_bf16(acc[mi][2 * ng],     ah[mi], bh[0], bh[1]);
                    mma_bf16(acc[mi][2 * ng],     al[mi], bh[0], bh[1]);
                    mma_bf16(acc[mi][2 * ng],     ah[mi], bl[0], bl[1]);
                    mma_bf16(acc[mi][2 * ng + 1], ah[mi], bh[2], bh[3]);
                    mma_bf16(acc[mi][2 * ng + 1], al[mi], bh[2], bh[3]);
                    mma_bf16(acc[mi][2 * ng + 1], ah[mi], bl[2], bl[3]);
                }
            }
        }
        __syncthreads();
    }

#pragma unroll
    for (int mi = 0; mi < 4; mi++) {
#pragma unroll
        for (int j = 0; j < 8; j++) {
            int row = m0 + wm * 64 + mi * 16 + (lane >> 2);
            int o = n0 + wn * 64 + j * 8 + (lane & 3) * 2;
            float b0 = bias[o], b1 = bias[o + 1];
#pragma unroll
            for (int half = 0; half < 2; half++) {
                int m = row + half * 8;
                float vx = acc[mi][j][half * 2] + b0;
                float vy = acc[mi][j][half * 2 + 1] + b1;
                if (EPI == 0) {
                    int s = o >> 10;
                    int rem = o & 1023;
                    int hh = rem >> 6;
                    int d = rem & 63;
                    int bb = m >> 11;
                    int t = m & 2047;
                    __nv_bfloat16 h0 = __float2bfloat16(vx);
                    __nv_bfloat16 l0 = __float2bfloat16(vx - __bfloat162float(h0));
                    __nv_bfloat16 h1 = __float2bfloat16(vy);
                    __nv_bfloat16 l1 = __float2bfloat16(vy - __bfloat162float(h1));
                    if (s == 2) {
                        size_t vi = ((size_t)(bb * HH + hh) * DH + d) * TT + t;
                        g_v_h[vi] = h0;      g_v_l[vi] = l0;
                        g_v_h[vi + TT] = h1; g_v_l[vi + TT] = l1;
                    } else {
                        size_t idx = (((size_t)(bb * HH + hh) * TT + t) * DH + d) >> 1;
                        __nv_bfloat162 hv(h0, h1), lv(l0, l1);
                        if (s == 0) { ((__nv_bfloat162*)g_q_h)[idx] = hv;
                                      ((__nv_bfloat162*)g_q_l)[idx] = lv; }
                        else        { ((__nv_bfloat162*)g_k_h)[idx] = hv;
                                      ((__nv_bfloat162*)g_k_l)[idx] = lv; }
                    }
                } else {
                    *(float2*)&Cout[(size_t)m * N + o] = make_float2(vx, vy);
                }
            }
        }
    }
}

// ---------------------------------------------------------------------------
// Flash attention: bf16x3 mma.sync, FMA fast-exp, TRIPLE-buffered cp.async,
// single __syncthreads per iteration.
// smem: Q 32KB | 3 x (KH|KL|VH|VL = 64KB) = 224KB
// ---------------------------------------------------------------------------
#define FQ_H  0
#define FQ_L  16384
#define FBUF0 32768
#define FBSZ  65536
#define F_KH  0
#define F_KL  16384
#define F_VH  32768
#define F_VL  49152
#define FL_SMEM 229376

__launch_bounds__(256, 1)
__global__ void flash_mma() {
    extern __shared__ char fsm[];
    const uint32_t sb = smem_u32(fsm);
    const int tid = threadIdx.x;
    const int wid = tid >> 5;
    const int lane = tid & 31;
    const int b = blockIdx.y >> 4;
    const int h = blockIdx.y & 15;
    const int i0 = blockIdx.x * 128;

    const int a_row = (lane & 7) + ((lane >> 3) & 1) * 8;
    const int a_kc  = lane >> 4;
    const int b_row = ((lane >> 4) * 8) + (lane & 7);
    const int b_kc  = (lane >> 3) & 1;

    const size_t qoff = (size_t)(b * HH + h) * TT * DH;
    const __nv_bfloat16* Qh = g_q_h + qoff + (size_t)i0 * DH;
    const __nv_bfloat16* Ql = g_q_l + qoff + (size_t)i0 * DH;
    const __nv_bfloat16* Kh = g_k_h + qoff;
    const __nv_bfloat16* Kl = g_k_l + qoff;
    const __nv_bfloat16* Vh = g_v_h + qoff;
    const __nv_bfloat16* Vl = g_v_l + qoff;
    const float* dec = g_decay + h * TT;

    // prologue: Q (group 0), tile0 (group 1), tile1 (group 2)
    gload_qk(Qh, sb + FQ_H, tid);
    gload_qk(Ql, sb + FQ_L, tid);
    CP_COMMIT();
    {
        const uint32_t d0 = sb + FBUF0;
        gload_qk(Kh, d0 + F_KH, tid);
        gload_qk(Kl, d0 + F_KL, tid);
        gload_vt(Vh, d0 + F_VH, tid);
        gload_vt(Vl, d0 + F_VL, tid);
        CP_COMMIT();
        const uint32_t d1 = sb + FBUF0 + FBSZ;
        gload_qk(Kh + 128 * DH, d1 + F_KH, tid);
        gload_qk(Kl + 128 * DH, d1 + F_KL, tid);
        gload_vt(Vh + 128, d1 + F_VH, tid);
        gload_vt(Vl + 128, d1 + F_VL, tid);
        CP_COMMIT();
    }
    CP_WAIT2();               // Q landed
    __syncthreads();

    uint32_t qh[4][4], ql[4][4];
#pragma unroll
    for (int kt = 0; kt < 4; kt++) {
        uint32_t off = swz((wid * 16 + a_row) * 128 + (kt * 2 + a_kc) * 16);
        ldmx4(qh[kt], sb + FQ_H + off);
        ldmx4(ql[kt], sb + FQ_L + off);
    }

    float O[8][4];
#pragma unroll
    for (int j = 0; j < 8; j++)
#pragma unroll
        for (int q = 0; q < 4; q++) O[j][q] = 0.f;
    float lsum0 = 0.f, lsum1 = 0.f;
    const float K1 = 0.125f * 1.44269504f;    // scale * log2(e)
    const int r_lo = i0 + wid * 16 + (lane >> 2);

    int bufc = 0;   // buffer index of tile c
    for (int c = 0; c < 16; c++) {
        if (c < 15) CP_WAIT1(); else CP_WAIT0();
        __syncthreads();      // tile c visible to all; all warps done with tile c-1

        if (c + 2 <= 15) {    // prefetch tile c+2 into buffer of tile c-1
            int bn = bufc + 2; if (bn >= 3) bn -= 3;
            const uint32_t dn = sb + FBUF0 + bn * FBSZ;
            const size_t j2 = (size_t)(c + 2) * 128;
            gload_qk(Kh + j2 * DH, dn + F_KH, tid);
            gload_qk(Kl + j2 * DH, dn + F_KL, tid);
            gload_vt(Vh + j2, dn + F_VH, tid);
            gload_vt(Vl + j2, dn + F_VL, tid);
            CP_COMMIT();
        }

        const uint32_t cur = sb + FBUF0 + bufc * FBSZ;
        const uint32_t sKh = cur + F_KH, sKl = cur + F_KL;
        const uint32_t sVh = cur + F_VH, sVl = cur + F_VL;
        const int j0 = c * 128;

        // S = Q K^T (bf16x3)
        float s[16][4];
#pragma unroll
        for (int j = 0; j < 16; j++)
#pragma unroll
            for (int q = 0; q < 4; q++) s[j][q] = 0.f;
#pragma unroll
        for (int kt = 0; kt < 4; kt++) {
#pragma unroll
            for (int ng = 0; ng < 8; ng++) {
                uint32_t kb[4], kc[4];
                uint32_t off = swz((ng * 16 + b_row) * 128 + (kt * 2 + b_kc) * 16);
                ldmx4(kb, sKh + off);
                ldmx4(kc, sKl + off);
                mma_bf16(s[2 * ng],     qh[kt], kb[0], kb[1]);
                mma_bf16(s[2 * ng],     ql[kt], kb[0], kb[1]);
                mma_bf16(s[2 * ng],     qh[kt], kc[0], kc[1]);
                mma_bf16(s[2 * ng + 1], qh[kt], kb[2], kb[3]);
                mma_bf16(s[2 * ng + 1], ql[kt], kb[2], kb[3]);
                mma_bf16(s[2 * ng + 1], qh[kt], kc[2], kc[3]);
            }
        }

        // p = exp2(s * scale*log2e * decay)
#pragma unroll
        for (int j = 0; j < 16; j++) {
            int cbase = j0 + j * 8 + (lane & 3) * 2;
#pragma unroll
            for (int cc = 0; cc < 4; cc++) {
                int rg = r_lo + ((cc >= 2) ? 8 : 0);
                int cg = cbase + (cc & 1);
                float dcy = __ldg(&dec[abs(rg - cg)]);
                float p = fexp2(s[j][cc] * dcy * K1);
                s[j][cc] = p;
                if (cc < 2) lsum0 += p; else lsum1 += p;
            }
        }

        // O += P V (bf16x3; P from registers)
#pragma unroll
        for (int kt = 0; kt < 8; kt++) {
            uint32_t ph[4], pl[4];
            ph[0] = pack_hl(s[2 * kt][0],     s[2 * kt][1],     pl[0]);
            ph[1] = pack_hl(s[2 * kt][2],     s[2 * kt][3],     pl[1]);
            ph[2] = pack_hl(s[2 * kt + 1][0], s[2 * kt + 1][1], pl[2]);
            ph[3] = pack_hl(s[2 * kt + 1][2], s[2 * kt + 1][3], pl[3]);
#pragma unroll
            for (int ng = 0; ng < 4; ng++) {
                uint32_t vh2[4], vl2[4];
                uint32_t off = swz256((ng * 16 + b_row) * 256 + (kt * 2 + b_kc) * 16);
                ldmx4(vh2, sVh + off);
                ldmx4(vl2, sVl + off);
                mma_bf16(O[2 * ng],     ph, vh2[0], vh2[1]);
                mma_bf16(O[2 * ng],     pl, vh2[0], vh2[1]);
                mma_bf16(O[2 * ng],     ph, vl2[0], vl2[1]);
                mma_bf16(O[2 * ng + 1], ph, vh2[2], vh2[3]);
                mma_bf16(O[2 * ng + 1], pl, vh2[2], vh2[3]);
                mma_bf16(O[2 * ng + 1], ph, vl2[2], vl2[3]);
            }
        }

        if (++bufc == 3) bufc = 0;
    }

    lsum0 += __shfl_xor_sync(0xffffffffu, lsum0, 1);
    lsum0 += __shfl_xor_sync(0xffffffffu, lsum0, 2);
    lsum1 += __shfl_xor_sync(0xffffffffu, lsum1, 1);
    lsum1 += __shfl_xor_sync(0xffffffffu, lsum1, 2);
    const float inv0 = 1.f / lsum0;
    const float inv1 = 1.f / lsum1;

#pragma unroll
    for (int j = 0; j < 8; j++) {
        int d = j * 8 + (lane & 3) * 2;
        size_t base0 = ((size_t)b * TT + (size_t)(r_lo)) * CC + h * DH + d;
        size_t base1 = base0 + 8 * CC;
        uint32_t lo;
        uint32_t hi = pack_hl(O[j][0] * inv0, O[j][1] * inv0, lo);
        ((uint32_t*)g_ao_h)[base0 >> 1] = hi;
        ((uint32_t*)g_ao_l)[base0 >> 1] = lo;
        hi = pack_hl(O[j][2] * inv1, O[j][3] * inv1, lo);
        ((uint32_t*)g_ao_h)[base1 >> 1] = hi;
        ((uint32_t*)g_ao_l)[base1 >> 1] = lo;
    }
}

// ---------------------------------------------------------------------------
extern "C" void kernel_launch(void* const* d_in, const int* in_sizes, int n_in,
                              void* d_out, int out_size) {
    const float* x = (const float*)d_in[0];
    const float* qkv_w = (const float*)d_in[1];
    const float* qkv_b = (const float*)d_in[2];
    const float* proj_w = (const float*)d_in[3];
    const float* proj_b = (const float*)d_in[4];
    const float* lambda_raw = (const float*)d_in[5];
    float* out = (float*)d_out;

    void *p_xh, *p_xl, *p_w1h, *p_w1l, *p_w2h, *p_w2l, *p_aoh, *p_aol;
    cudaGetSymbolAddress(&p_xh, g_x_h);   cudaGetSymbolAddress(&p_xl, g_x_l);
    cudaGetSymbolAddress(&p_w1h, g_w1_h); cudaGetSymbolAddress(&p_w1l, g_w1_l);
    cudaGetSymbolAddress(&p_w2h, g_w2_h); cudaGetSymbolAddress(&p_w2l, g_w2_l);
    cudaGetSymbolAddress(&p_aoh, g_ao_h); cudaGetSymbolAddress(&p_aol, g_ao_l);

    cudaFuncSetAttribute(flash_mma, cudaFuncAttributeMaxDynamicSharedMemorySize, FL_SMEM);
    cudaFuncSetAttribute(gemm_mma<0>, cudaFuncAttributeMaxDynamicSharedMemorySize, GEMM_SMEM);
    cudaFuncSetAttribute(gemm_mma<1>, cudaFuncAttributeMaxDynamicSharedMemorySize, GEMM_SMEM);

    decay_kernel<<<(HH * TT + 255) / 256, 256>>>(lambda_raw);

    split_bf16<<<4194304 / 4 / 256, 256>>>(x, (__nv_bfloat16*)p_xh, (__nv_bfloat16*)p_xl,
                                           4194304 / 4);
    split_bf16<<<3145728 / 4 / 256, 256>>>(qkv_w, (__nv_bfloat16*)p_w1h, (__nv_bfloat16*)p_w1l,
                                           3145728 / 4);
    split_bf16<<<1048576 / 4 / 256, 256>>>(proj_w, (__nv_bfloat16*)p_w2h, (__nv_bfloat16*)p_w2l,
                                           1048576 / 4);

    // QKV: M=4096 (256-row tiles), N=3072
    gemm_mma<0><<<dim3(3072 / 128, 4096 / 256), 256, GEMM_SMEM>>>(
        (const __nv_bfloat16*)p_xh, (const __nv_bfloat16*)p_xl,
        (const __nv_bfloat16*)p_w1h, (const __nv_bfloat16*)p_w1l, qkv_b, nullptr, 3072);

    flash_mma<<<dim3(TT / 128, BB * HH), 256, FL_SMEM>>>();

    // Proj: M=4096, N=1024 -> 128 CTAs (~1 wave)
    gemm_mma<1><<<dim3(1024 / 128, 4096 / 256), 256, GEMM_SMEM>>>(
        (const __nv_bfloat16*)p_aoh, (const __nv_bfloat16*)p_aol,
        (const __nv_bfloat16*)p_w2h, (const __nv_bfloat16*)p_w2l, proj_b, out, 1024);
}

// round 8
// speedup vs baseline: 3.0232x; 1.0055x over previous
#include <cuda_runtime.h>
#include <cuda_bf16.h>
#include <math.h>
#include <stdint.h>

#define BB 2
#define TT 2048
#define CC 1024
#define HH 16
#define DH 64

// ---------------------------------------------------------------------------
// Scratch (device globals: allocation-free rule)
// ---------------------------------------------------------------------------
__device__ float g_decay[HH * TT];                 // [h][dist]

__device__ __nv_bfloat16 g_q_h[4194304], g_q_l[4194304];
__device__ __nv_bfloat16 g_k_h[4194304], g_k_l[4194304];
__device__ __nv_bfloat16 g_v_h[4194304], g_v_l[4194304];   // V^T [b][h][d][t]
__device__ __nv_bfloat16 g_ao_h[4194304], g_ao_l[4194304];

__device__ __nv_bfloat16 g_x_h[4194304],  g_x_l[4194304];
__device__ __nv_bfloat16 g_w1_h[3145728], g_w1_l[3145728];
__device__ __nv_bfloat16 g_w2_h[1048576], g_w2_l[1048576];

// ---------------------------------------------------------------------------
// helpers
// ---------------------------------------------------------------------------
__device__ __forceinline__ uint32_t smem_u32(const void* p) {
    uint32_t a;
    asm("{ .reg .u64 t; cvta.to.shared.u64 t, %1; cvt.u32.u64 %0, t; }" : "=r"(a) : "l"(p));
    return a;
}
__device__ __forceinline__ uint32_t swz(uint32_t off) {     // 128B rows
    return off ^ ((off >> 3) & 0x70);
}
__device__ __forceinline__ void ldmx4(uint32_t* r, uint32_t addr) {
    asm volatile("ldmatrix.sync.aligned.m8n8.x4.shared.b16 {%0,%1,%2,%3}, [%4];"
                 : "=r"(r[0]), "=r"(r[1]), "=r"(r[2]), "=r"(r[3]) : "r"(addr));
}
__device__ __forceinline__ void mma_bf16(float* c, const uint32_t* a, uint32_t b0, uint32_t b1) {
    asm volatile("mma.sync.aligned.m16n8k16.row.col.f32.bf16.bf16.f32 "
                 "{%0,%1,%2,%3}, {%4,%5,%6,%7}, {%8,%9}, {%0,%1,%2,%3};"
                 : "+f"(c[0]), "+f"(c[1]), "+f"(c[2]), "+f"(c[3])
                 : "r"(a[0]), "r"(a[1]), "r"(a[2]), "r"(a[3]), "r"(b0), "r"(b1));
}
__device__ __forceinline__ void cpa16(uint32_t dst, const void* src) {
    asm volatile("cp.async.cg.shared.global [%0], [%1], 16;" :: "r"(dst), "l"(src));
}
#define CP_COMMIT() asm volatile("cp.async.commit_group;" ::: "memory")
#define CP_WAIT1()  asm volatile("cp.async.wait_group 1;" ::: "memory")
#define CP_WAIT0()  asm volatile("cp.async.wait_group 0;" ::: "memory")

// fast 2^y via FMA only (no MUFU)
__device__ __forceinline__ float fexp2(float y) {
    y = fminf(fmaxf(y, -120.f), 80.f);
    float z = y + 12582912.f;
    int iz = __float_as_int(z);
    float f = y - (z - 12582912.f);
    float p = 1.3333558e-3f;
    p = fmaf(p, f, 9.6181291e-3f);
    p = fmaf(p, f, 5.5504109e-2f);
    p = fmaf(p, f, 2.4022651e-1f);
    p = fmaf(p, f, 6.9314718e-1f);
    p = fmaf(p, f, 1.0f);
    return p * __int_as_float((iz + (127 - 0x4B400000)) << 23);
}
__device__ __forceinline__ uint32_t pack_hl(float x, float y, uint32_t& lo) {
    __nv_bfloat16 hx = __float2bfloat16(x), hy = __float2bfloat16(y);
    __nv_bfloat16 lx = __float2bfloat16(x - __bfloat162float(hx));
    __nv_bfloat16 ly = __float2bfloat16(y - __bfloat162float(hy));
    lo = ((uint32_t)__bfloat16_as_ushort(ly) << 16) | (uint32_t)__bfloat16_as_ushort(lx);
    return ((uint32_t)__bfloat16_as_ushort(hy) << 16) | (uint32_t)__bfloat16_as_ushort(hx);
}

// ---------------------------------------------------------------------------
__global__ void split_bf16(const float* __restrict__ src, __nv_bfloat16* __restrict__ hi,
                           __nv_bfloat16* __restrict__ lo, int n4) {
    int i = blockIdx.x * blockDim.x + threadIdx.x;
    if (i < n4) {
        float4 v = ((const float4*)src)[i];
        __nv_bfloat16 h0 = __float2bfloat16(v.x), h1 = __float2bfloat16(v.y);
        __nv_bfloat16 h2 = __float2bfloat16(v.z), h3 = __float2bfloat16(v.w);
        __nv_bfloat162* H = (__nv_bfloat162*)hi;
        __nv_bfloat162* L = (__nv_bfloat162*)lo;
        H[i * 2]     = __nv_bfloat162(h0, h1);
        H[i * 2 + 1] = __nv_bfloat162(h2, h3);
        L[i * 2]     = __nv_bfloat162(__float2bfloat16(v.x - __bfloat162float(h0)),
                                      __float2bfloat16(v.y - __bfloat162float(h1)));
        L[i * 2 + 1] = __nv_bfloat162(__float2bfloat16(v.z - __bfloat162float(h2)),
                                      __float2bfloat16(v.w - __bfloat162float(h3)));
    }
}

__global__ void decay_kernel(const float* __restrict__ lambda_raw) {
    int idx = blockIdx.x * blockDim.x + threadIdx.x;
    if (idx < HH * TT) {
        int h = idx / TT;
        int d = idx % TT;
        float lam = log1pf(expf(lambda_raw[h]));
        g_decay[idx] = expf(-lam * (float)d);
    }
}

// ---------------------------------------------------------------------------
// async tile loaders
// ---------------------------------------------------------------------------
__device__ __forceinline__ void gload_a256(const __nv_bfloat16* __restrict__ g,
                                           uint32_t dst, int tid) {
#pragma unroll
    for (int i = 0; i < 8; i++) {
        int slot = tid + i * 256;
        int row = slot >> 3;
        int c16 = slot & 7;
        cpa16(dst + swz(row * 128 + c16 * 16), g + (size_t)row * 1024 + c16 * 8);
    }
}
__device__ __forceinline__ void gload_b128(const __nv_bfloat16* __restrict__ g,
                                           uint32_t dst, int tid) {
#pragma unroll
    for (int i = 0; i < 4; i++) {
        int slot = tid + i * 256;
        int row = slot >> 3;
        int c16 = slot & 7;
        cpa16(dst + swz(row * 128 + c16 * 16), g + (size_t)row * 1024 + c16 * 8);
    }
}
__device__ __forceinline__ void gload_q128(const __nv_bfloat16* __restrict__ g,
                                           uint32_t dst, int tid) {
    // 128 rows x 64 bf16 contiguous (16KB = 1024 chunks)
#pragma unroll
    for (int i = 0; i < 4; i++) {
        int slot = tid + i * 256;
        int row = slot >> 3;
        int c16 = slot & 7;
        cpa16(dst + swz(row * 128 + c16 * 16), g + (size_t)row * 64 + c16 * 8);
    }
}
__device__ __forceinline__ void gload_k64(const __nv_bfloat16* __restrict__ g,
                                          uint32_t dst, int tid) {
    // 64 rows x 64 bf16 contiguous (8KB = 512 chunks; 2 per thread)
#pragma unroll
    for (int i = 0; i < 2; i++) {
        int slot = tid + i * 256;
        int row = slot >> 3;
        int c16 = slot & 7;
        cpa16(dst + swz(row * 128 + c16 * 16), g + (size_t)row * 64 + c16 * 8);
    }
}
__device__ __forceinline__ void gload_v64(const __nv_bfloat16* __restrict__ g,
                                          uint32_t dst, int tid) {
    // 64 d-rows x 64 t-cols, gmem row stride 2048 (8KB = 512 chunks; 2 per thread)
#pragma unroll
    for (int i = 0; i < 2; i++) {
        int slot = tid + i * 256;
        int row = slot >> 3;
        int c16 = slot & 7;
        cpa16(dst + swz(row * 128 + c16 * 16), g + (size_t)row * 2048 + c16 * 8);
    }
}

// ---------------------------------------------------------------------------
// bf16x3 mma.sync NT GEMM, 256x128 CTA tile, BK=64, double-buffered (unchanged)
// ---------------------------------------------------------------------------
#define GA_H 0
#define GA_L 32768
#define GB_H 65536
#define GB_L 81920
#define GBUF 98304
#define GEMM_SMEM 196608

template <int EPI>
__launch_bounds__(256, 1)
__global__ void gemm_mma(const __nv_bfloat16* __restrict__ Ah, const __nv_bfloat16* __restrict__ Al,
                         const __nv_bfloat16* __restrict__ Bh, const __nv_bfloat16* __restrict__ Bl,
                         const float* __restrict__ bias, float* __restrict__ Cout, int N) {
    extern __shared__ char smem[];
    const uint32_t sb = smem_u32(smem);
    const int tid = threadIdx.x;
    const int wid = tid >> 5;
    const int lane = tid & 31;
    const int wm = wid & 3;
    const int wn = wid >> 2;
    const int n0 = blockIdx.x * 128;
    const int m0 = blockIdx.y * 256;

    const int a_row = (lane & 7) + ((lane >> 3) & 1) * 8;
    const int a_kc  = lane >> 4;
    const int b_row = ((lane >> 4) * 8) + (lane & 7);
    const int b_kc  = (lane >> 3) & 1;

    const __nv_bfloat16* Abase_h = Ah + (size_t)m0 * 1024;
    const __nv_bfloat16* Abase_l = Al + (size_t)m0 * 1024;
    const __nv_bfloat16* Bbase_h = Bh + (size_t)n0 * 1024;
    const __nv_bfloat16* Bbase_l = Bl + (size_t)n0 * 1024;

    float acc[4][8][4];
#pragma unroll
    for (int i = 0; i < 4; i++)
#pragma unroll
        for (int j = 0; j < 8; j++)
#pragma unroll
            for (int q = 0; q < 4; q++) acc[i][j][q] = 0.f;

    gload_a256(Abase_h, sb + GA_H, tid);
    gload_a256(Abase_l, sb + GA_L, tid);
    gload_b128(Bbase_h, sb + GB_H, tid);
    gload_b128(Bbase_l, sb + GB_L, tid);
    CP_COMMIT();

    for (int c = 0; c < 16; c++) {
        const uint32_t cur = (c & 1) ? GBUF : 0u;
        const uint32_t nxt = cur ^ GBUF;
        if (c < 15) {
            const size_t ka = (size_t)(c + 1) * 64;
            gload_a256(Abase_h + ka, sb + nxt + GA_H, tid);
            gload_a256(Abase_l + ka, sb + nxt + GA_L, tid);
            gload_b128(Bbase_h + ka, sb + nxt + GB_H, tid);
            gload_b128(Bbase_l + ka, sb + nxt + GB_L, tid);
            CP_COMMIT();
            CP_WAIT1();
        } else {
            CP_WAIT0();
        }
        __syncthreads();

        const uint32_t sAh = sb + cur + GA_H, sAl = sb + cur + GA_L;
        const uint32_t sBh = sb + cur + GB_H, sBl = sb + cur + GB_L;
#pragma unroll
        for (int kt = 0; kt < 4; kt++) {
            uint32_t ah[4][4], al[4][4];
#pragma unroll
            for (int mi = 0; mi < 4; mi++) {
                uint32_t off = swz((wm * 64 + mi * 16 + a_row) * 128 + (kt * 2 + a_kc) * 16);
                ldmx4(ah[mi], sAh + off);
                ldmx4(al[mi], sAl + off);
            }
#pragma unroll
            for (int ng = 0; ng < 4; ng++) {
                uint32_t bh[4], bl[4];
                uint32_t off = swz((wn * 64 + ng * 16 + b_row) * 128 + (kt * 2 + b_kc) * 16);
                ldmx4(bh, sBh + off);
                ldmx4(bl, sBl + off);
#pragma unroll
                for (int mi = 0; mi < 4; mi++) {
                    mma_bf16(acc[mi][2 * ng],     ah[mi], bh[0], bh[1]);
                    mma_bf16(acc[mi][2 * ng],     al[mi], bh[0], bh[1]);
                    mma_bf16(acc[mi][2 * ng],     ah[mi], bl[0], bl[1]);
                    mma_bf16(acc[mi][2 * ng + 1], ah[mi], bh[2], bh[3]);
                    mma_bf16(acc[mi][2 * ng + 1], al[mi], bh[2], bh[3]);
                    mma_bf16(acc[mi][2 * ng + 1], ah[mi], bl[2], bl[3]);
                }
            }
        }
        __syncthreads();
    }

#pragma unroll
    for (int mi = 0; mi < 4; mi++) {
#pragma unroll
        for (int j = 0; j < 8; j++) {
            int row = m0 + wm * 64 + mi * 16 + (lane >> 2);
            int o = n0 + wn * 64 + j * 8 + (lane & 3) * 2;
            float b0 = bias[o], b1 = bias[o + 1];
#pragma unroll
            for (int half = 0; half < 2; half++) {
                int m = row + half * 8;
                float vx = acc[mi][j][half * 2] + b0;
                float vy = acc[mi][j][half * 2 + 1] + b1;
                if (EPI == 0) {
                    int s = o >> 10;
                    int rem = o & 1023;
                    int hh = rem >> 6;
                    int d = rem & 63;
                    int bb = m >> 11;
                    int t = m & 2047;
                    __nv_bfloat16 h0 = __float2bfloat16(vx);
                    __nv_bfloat16 l0 = __float2bfloat16(vx - __bfloat162float(h0));
                    __nv_bfloat16 h1 = __float2bfloat16(vy);
                    __nv_bfloat16 l1 = __float2bfloat16(vy - __bfloat162float(h1));
                    if (s == 2) {
                        size_t vi = ((size_t)(bb * HH + hh) * DH + d) * TT + t;
                        g_v_h[vi] = h0;      g_v_l[vi] = l0;
                        g_v_h[vi + TT] = h1; g_v_l[vi + TT] = l1;
                    } else {
                        size_t idx = (((size_t)(bb * HH + hh) * TT + t) * DH + d) >> 1;
                        __nv_bfloat162 hv(h0, h1), lv(l0, l1);
                        if (s == 0) { ((__nv_bfloat162*)g_q_h)[idx] = hv;
                                      ((__nv_bfloat162*)g_q_l)[idx] = lv; }
                        else        { ((__nv_bfloat162*)g_k_h)[idx] = hv;
                                      ((__nv_bfloat162*)g_k_l)[idx] = lv; }
                    }
                } else {
                    *(float2*)&Cout[(size_t)m * N + o] = make_float2(vx, vy);
                }
            }
        }
    }
}

// ---------------------------------------------------------------------------
// Flash attention: bf16x3 mma.sync, FMA fast-exp.
// 64-col KV tiles, double-buffered, 96KB smem -> 2 CTAs/SM (4 warps/SMSP).
// Q-hi fragments in registers; Q-lo re-ldmatrix'd from smem each tile.
// smem: QH 16K | QL 16K | 2 x (KH 8K | KL 8K | VH 8K | VL 8K) = 96KB
// ---------------------------------------------------------------------------
#define FQ_H  0
#define FQ_L  16384
#define FBUF0 32768
#define FBSZ  32768
#define F_KH  0
#define F_KL  8192
#define F_VH  16384
#define F_VL  24576
#define FL_SMEM 98304

__launch_bounds__(256, 2)
__global__ void flash_mma() {
    extern __shared__ char fsm[];
    const uint32_t sb = smem_u32(fsm);
    const int tid = threadIdx.x;
    const int wid = tid >> 5;
    const int lane = tid & 31;
    const int b = blockIdx.y >> 4;
    const int h = blockIdx.y & 15;
    const int i0 = blockIdx.x * 128;

    const int a_row = (lane & 7) + ((lane >> 3) & 1) * 8;
    const int a_kc  = lane >> 4;
    const int b_row = ((lane >> 4) * 8) + (lane & 7);
    const int b_kc  = (lane >> 3) & 1;

    const size_t qoff = (size_t)(b * HH + h) * TT * DH;
    const __nv_bfloat16* Qh = g_q_h + qoff + (size_t)i0 * DH;
    const __nv_bfloat16* Ql = g_q_l + qoff + (size_t)i0 * DH;
    const __nv_bfloat16* Kh = g_k_h + qoff;
    const __nv_bfloat16* Kl = g_k_l + qoff;
    const __nv_bfloat16* Vh = g_v_h + qoff;
    const __nv_bfloat16* Vl = g_v_l + qoff;
    const float* dec = g_decay + h * TT;

    // prologue: Q (group 0), tile0 -> buf0 (group 1)
    gload_q128(Qh, sb + FQ_H, tid);
    gload_q128(Ql, sb + FQ_L, tid);
    CP_COMMIT();
    {
        const uint32_t d0 = sb + FBUF0;
        gload_k64(Kh, d0 + F_KH, tid);
        gload_k64(Kl, d0 + F_KL, tid);
        gload_v64(Vh, d0 + F_VH, tid);
        gload_v64(Vl, d0 + F_VL, tid);
        CP_COMMIT();
    }
    CP_WAIT1();               // Q landed
    __syncthreads();

    uint32_t qh[4][4];        // Q-hi persistent; Q-lo reloaded per tile
#pragma unroll
    for (int kt = 0; kt < 4; kt++) {
        uint32_t off = swz((wid * 16 + a_row) * 128 + (kt * 2 + a_kc) * 16);
        ldmx4(qh[kt], sb + FQ_H + off);
    }

    float O[8][4];
#pragma unroll
    for (int j = 0; j < 8; j++)
#pragma unroll
        for (int q = 0; q < 4; q++) O[j][q] = 0.f;
    float lsum0 = 0.f, lsum1 = 0.f;
    const float K1 = 0.125f * 1.44269504f;    // scale * log2(e)
    const int r_lo = i0 + wid * 16 + (lane >> 2);

    for (int c = 0; c < 32; c++) {            // 64-wide KV tiles
        CP_WAIT0();           // tile c arrived
        __syncthreads();      // all warps done with tile c-1 -> its buffer is free

        if (c < 31) {
            const uint32_t dn = sb + FBUF0 + ((c + 1) & 1) * FBSZ;
            const size_t j1 = (size_t)(c + 1) * 64;
            gload_k64(Kh + j1 * DH, dn + F_KH, tid);
            gload_k64(Kl + j1 * DH, dn + F_KL, tid);
            gload_v64(Vh + j1, dn + F_VH, tid);
            gload_v64(Vl + j1, dn + F_VL, tid);
            CP_COMMIT();
        }

        const uint32_t cur = sb + FBUF0 + (c & 1) * FBSZ;
        const uint32_t sKh = cur + F_KH, sKl = cur + F_KL;
        const uint32_t sVh = cur + F_VH, sVl = cur + F_VL;
        const int j0 = c * 64;

        // S = Q K^T (bf16x3), 16x64 tile
        float s[8][4];
#pragma unroll
        for (int j = 0; j < 8; j++)
#pragma unroll
            for (int q = 0; q < 4; q++) s[j][q] = 0.f;
#pragma unroll
        for (int kt = 0; kt < 4; kt++) {
            uint32_t qlt[4];
            ldmx4(qlt, sb + FQ_L + swz((wid * 16 + a_row) * 128 + (kt * 2 + a_kc) * 16));
#pragma unroll
            for (int ng = 0; ng < 4; ng++) {
                uint32_t kb[4], kc[4];
                uint32_t off = swz((ng * 16 + b_row) * 128 + (kt * 2 + b_kc) * 16);
                ldmx4(kb, sKh + off);
                ldmx4(kc, sKl + off);
                mma_bf16(s[2 * ng],     qh[kt], kb[0], kb[1]);
                mma_bf16(s[2 * ng],     qlt,    kb[0], kb[1]);
                mma_bf16(s[2 * ng],     qh[kt], kc[0], kc[1]);
                mma_bf16(s[2 * ng + 1], qh[kt], kb[2], kb[3]);
                mma_bf16(s[2 * ng + 1], qlt,    kb[2], kb[3]);
                mma_bf16(s[2 * ng + 1], qh[kt], kc[2], kc[3]);
            }
        }

        // p = exp2(s * scale*log2e * decay)
#pragma unroll
        for (int j = 0; j < 8; j++) {
            int cbase = j0 + j * 8 + (lane & 3) * 2;
#pragma unroll
            for (int cc = 0; cc < 4; cc++) {
                int rg = r_lo + ((cc >= 2) ? 8 : 0);
                int cg = cbase + (cc & 1);
                float dcy = __ldg(&dec[abs(rg - cg)]);
                float p = fexp2(s[j][cc] * dcy * K1);
                s[j][cc] = p;
                if (cc < 2) lsum0 += p; else lsum1 += p;
            }
        }

        // O += P V (bf16x3; P from registers)
#pragma unroll
        for (int kt = 0; kt < 4; kt++) {
            uint32_t ph[4], pl[4];
            ph[0] = pack_hl(s[2 * kt][0],     s[2 * kt][1],     pl[0]);
            ph[1] = pack_hl(s[2 * kt][2],     s[2 * kt][3],     pl[1]);
            ph[2] = pack_hl(s[2 * kt + 1][0], s[2 * kt + 1][1], pl[2]);
            ph[3] = pack_hl(s[2 * kt + 1][2], s[2 * kt + 1][3], pl[3]);
#pragma unroll
            for (int ng = 0; ng < 4; ng++) {
                uint32_t vh2[4], vl2[4];
                uint32_t off = swz((ng * 16 + b_row) * 128 + (kt * 2 + b_kc) * 16);
                ldmx4(vh2, sVh + off);
                ldmx4(vl2, sVl + off);
                mma_bf16(O[2 * ng],     ph, vh2[0], vh2[1]);
                mma_bf16(O[2 * ng],     pl, vh2[0], vh2[1]);
                mma_bf16(O[2 * ng],     ph, vl2[0], vl2[1]);
                mma_bf16(O[2 * ng + 1], ph, vh2[2], vh2[3]);
                mma_bf16(O[2 * ng + 1], pl, vh2[2], vh2[3]);
                mma_bf16(O[2 * ng + 1], ph, vl2[2], vl2[3]);
            }
        }
    }

    lsum0 += __shfl_xor_sync(0xffffffffu, lsum0, 1);
    lsum0 += __shfl_xor_sync(0xffffffffu, lsum0, 2);
    lsum1 += __shfl_xor_sync(0xffffffffu, lsum1, 1);
    lsum1 += __shfl_xor_sync(0xffffffffu, lsum1, 2);
    const float inv0 = 1.f / lsum0;
    const float inv1 = 1.f / lsum1;

#pragma unroll
    for (int j = 0; j < 8; j++) {
        int d = j * 8 + (lane & 3) * 2;
        size_t base0 = ((size_t)b * TT + (size_t)(r_lo)) * CC + h * DH + d;
        size_t base1 = base0 + 8 * CC;
        uint32_t lo;
        uint32_t hi = pack_hl(O[j][0] * inv0, O[j][1] * inv0, lo);
        ((uint32_t*)g_ao_h)[base0 >> 1] = hi;
        ((uint32_t*)g_ao_l)[base0 >> 1] = lo;
        hi = pack_hl(O[j][2] * inv1, O[j][3] * inv1, lo);
        ((uint32_t*)g_ao_h)[base1 >> 1] = hi;
        ((uint32_t*)g_ao_l)[base1 >> 1] = lo;
    }
}

// ---------------------------------------------------------------------------
extern "C" void kernel_launch(void* const* d_in, const int* in_sizes, int n_in,
                              void* d_out, int out_size) {
    const float* x = (const float*)d_in[0];
    const float* qkv_w = (const float*)d_in[1];
    const float* qkv_b = (const float*)d_in[2];
    const float* proj_w = (const float*)d_in[3];
    const float* proj_b = (const float*)d_in[4];
    const float* lambda_raw = (const float*)d_in[5];
    float* out = (float*)d_out;

    void *p_xh, *p_xl, *p_w1h, *p_w1l, *p_w2h, *p_w2l, *p_aoh, *p_aol;
    cudaGetSymbolAddress(&p_xh, g_x_h);   cudaGetSymbolAddress(&p_xl, g_x_l);
    cudaGetSymbolAddress(&p_w1h, g_w1_h); cudaGetSymbolAddress(&p_w1l, g_w1_l);
    cudaGetSymbolAddress(&p_w2h, g_w2_h); cudaGetSymbolAddress(&p_w2l, g_w2_l);
    cudaGetSymbolAddress(&p_aoh, g_ao_h); cudaGetSymbolAddress(&p_aol, g_ao_l);

    cudaFuncSetAttribute(flash_mma, cudaFuncAttributeMaxDynamicSharedMemorySize, FL_SMEM);
    cudaFuncSetAttribute(gemm_mma<0>, cudaFuncAttributeMaxDynamicSharedMemorySize, GEMM_SMEM);
    cudaFuncSetAttribute(gemm_mma<1>, cudaFuncAttributeMaxDynamicSharedMemorySize, GEMM_SMEM);

    decay_kernel<<<(HH * TT + 255) / 256, 256>>>(lambda_raw);

    split_bf16<<<4194304 / 4 / 256, 256>>>(x, (__nv_bfloat16*)p_xh, (__nv_bfloat16*)p_xl,
                                           4194304 / 4);
    split_bf16<<<3145728 / 4 / 256, 256>>>(qkv_w, (__nv_bfloat16*)p_w1h, (__nv_bfloat16*)p_w1l,
                                           3145728 / 4);
    split_bf16<<<1048576 / 4 / 256, 256>>>(proj_w, (__nv_bfloat16*)p_w2h, (__nv_bfloat16*)p_w2l,
                                           1048576 / 4);

    gemm_mma<0><<<dim3(3072 / 128, 4096 / 256), 256, GEMM_SMEM>>>(
        (const __nv_bfloat16*)p_xh, (const __nv_bfloat16*)p_xl,
        (const __nv_bfloat16*)p_w1h, (const __nv_bfloat16*)p_w1l, qkv_b, nullptr, 3072);

    flash_mma<<<dim3(TT / 128, BB * HH), 256, FL_SMEM>>>();

    gemm_mma<1><<<dim3(1024 / 128, 4096 / 256), 256, GEMM_SMEM>>>(
        (const __nv_bfloat16*)p_aoh, (const __nv_bfloat16*)p_aol,
        (const __nv_bfloat16*)p_w2h, (const __nv_bfloat16*)p_w2l, proj_b, out, 1024);
}